// round 14
// baseline (speedup 1.0000x reference)
#include <cuda_runtime.h>
#include <cuda_bf16.h>
#include <cuda_fp16.h>
#include <cstdint>

#define BB 2
#define TT 1024
#define DD 1024
#define VV 32000
#define LL 8
#define MD (TT * DD)
#define AA (TT * TT)

typedef __nv_bfloat16 bf16;

__device__ float g_x[BB * MD];
__device__ float g_a[BB * AA];
__device__ float g_o[BB * MD];
__device__ bf16 g_xh[BB * MD], g_xl[BB * MD];
__device__ bf16 g_qh[BB * MD], g_ql[BB * MD];
__device__ bf16 g_kh[BB * MD], g_kl[BB * MD];
__device__ bf16 g_qwh[LL * DD * DD], g_qwl[LL * DD * DD];
__device__ bf16 g_kwh[LL * DD * DD], g_kwl[LL * DD * DD];
__device__ __half g_xf[BB * MD];
__device__ __half g_vf[BB * MD];          // V^T [b][d][t]
__device__ __half g_wf[BB * AA];
__device__ __half g_vwf[LL * DD * DD];
__device__ __half g_dwf[VV * DD];
__device__ __half g_xnf[BB * MD];

// 64B rows + XOR swizzle: chunk c (16B) of row r at r*64 + (c ^ ((r>>1)&3))*16.
#define SWZ(r, c) ((((uint32_t)(r)) << 6) + ((((c) ^ (((r) >> 1) & 3))) << 4))

__device__ __forceinline__ uint32_t smem_u32(const void* p) {
    uint32_t a;
    asm("{ .reg .u64 t; cvta.to.shared.u64 t, %1; cvt.u32.u64 %0, t; }" : "=r"(a) : "l"(p));
    return a;
}
#define LDM4(r0, r1, r2, r3, ad) \
    asm volatile("ldmatrix.sync.aligned.m8n8.x4.shared.b16 {%0,%1,%2,%3},[%4];" \
                 : "=r"(r0), "=r"(r1), "=r"(r2), "=r"(r3) : "r"(ad))
#define MMA16B(c, a, b0_, b1_) \
    asm volatile("mma.sync.aligned.m16n8k16.row.col.f32.bf16.bf16.f32 " \
                 "{%0,%1,%2,%3},{%4,%5,%6,%7},{%8,%9},{%0,%1,%2,%3};" \
                 : "+f"((c)[0]), "+f"((c)[1]), "+f"((c)[2]), "+f"((c)[3]) \
                 : "r"((a)[0]), "r"((a)[1]), "r"((a)[2]), "r"((a)[3]), "r"(b0_), "r"(b1_))
#define MMA16H(c, a, b0_, b1_) \
    asm volatile("mma.sync.aligned.m16n8k16.row.col.f32.f16.f16.f32 " \
                 "{%0,%1,%2,%3},{%4,%5,%6,%7},{%8,%9},{%0,%1,%2,%3};" \
                 : "+f"((c)[0]), "+f"((c)[1]), "+f"((c)[2]), "+f"((c)[3]) \
                 : "r"((a)[0]), "r"((a)[1]), "r"((a)[2]), "r"((a)[3]), "r"(b0_), "r"(b1_))
#define CPA16(d, s) asm volatile("cp.async.cg.shared.global [%0], [%1], 16;" :: "r"(d), "l"(s))
#define CPCOMMIT()  asm volatile("cp.async.commit_group;" ::: "memory")
#define CPWAIT1()   asm volatile("cp.async.wait_group 1;" ::: "memory")
#define CPWAIT0()   asm volatile("cp.async.wait_group 0;" ::: "memory")

__device__ __forceinline__ void bsplit(float v, bf16& h, bf16& l) {
    h = __float2bfloat16_rn(v);
    l = __float2bfloat16_rn(v - __bfloat162float(h));
}

// ---------------------------------------------------------------------------
// Split core A (qkv): MT=128, 512 thr (4x4 warps of 32x32), BK=64 stages,
// 3-stage pipeline, loads issued 2 ahead. smem = 196608 B. [R12 proven]
// BIAS: 0 none, 1 per-N.  OUT: 0 fp32 Cf, 1 bf16 hi/lo Ch/Cl.
// ---------------------------------------------------------------------------
template <int BIAS, int OUT>
__device__ __forceinline__ void gemm_core(
    const bf16* __restrict__ Ah, const bf16* __restrict__ Al, int lda,
    const bf16* __restrict__ Bh, const bf16* __restrict__ Bl, int ldb,
    const float* __restrict__ bias,
    float* __restrict__ Cf, bf16* __restrict__ Ch, bf16* __restrict__ Cl, int ldc,
    int m0, int n0, int Keff)
{
    constexpr int ABY = 128 * 64;
    constexpr int BBY = 8192;
    constexpr int STG32 = 2 * ABY + 2 * BBY;
    constexpr int STG64 = 2 * STG32;
    extern __shared__ uint16_t sm[];
    const uint32_t sb = smem_u32(sm);
    const int tid = threadIdx.x, lane = tid & 31, wrp = tid >> 5;
    const int wm = wrp >> 2, wn = wrp & 3;
    const int S2 = Keff >> 6;

    const int a_ml = (lane & 7) + ((lane >> 3) & 1) * 8;
    const int a_c0 = lane >> 4;
    const int b_nl = (lane & 7) + ((lane >> 4) << 3);
    const int b_c0 = (lane >> 3) & 1;

    const int row = tid >> 2, ch = tid & 3;
    const bf16* Aph = Ah + (long)(m0 + row) * lda + ch * 8;
    const bf16* Apl = Al + (long)(m0 + row) * lda + ch * 8;
    const bf16* Bph = Bh + (long)(n0 + row) * ldb + ch * 8;
    const bf16* Bpl = Bl + (long)(n0 + row) * ldb + ch * 8;
    const uint32_t swz = SWZ(row, ch);

    auto issue32 = [&](int k32, uint32_t db) {
        const int k0 = k32 << 5;
        CPA16(db + swz,                 Aph + k0);
        CPA16(db + ABY + swz,           Apl + k0);
        CPA16(db + 2 * ABY + swz,       Bph + k0);
        CPA16(db + 2 * ABY + BBY + swz, Bpl + k0);
    };
    auto issue = [&](int s2) {
        const uint32_t db = sb + (uint32_t)(s2 % 3) * STG64;
        issue32(2 * s2, db);
        issue32(2 * s2 + 1, db + STG32);
        CPCOMMIT();
    };

    float acc[2][4][4] = {};

    auto compute32 = [&](uint32_t stb) {
        const uint32_t ahb = stb, alb = stb + ABY, bhb = stb + 2 * ABY, blb = bhb + BBY;
#pragma unroll
        for (int ks = 0; ks < 2; ks++) {
            uint32_t bhf[8], blf[8];
#pragma unroll
            for (int p = 0; p < 2; p++) {
                const uint32_t boff = SWZ(wn * 32 + p * 16 + b_nl, ks * 2 + b_c0);
                LDM4(bhf[p * 4 + 0], bhf[p * 4 + 1], bhf[p * 4 + 2], bhf[p * 4 + 3], bhb + boff);
                LDM4(blf[p * 4 + 0], blf[p * 4 + 1], blf[p * 4 + 2], blf[p * 4 + 3], blb + boff);
            }
#pragma unroll
            for (int mt = 0; mt < 2; mt++) {
                uint32_t ahf[4], alf[4];
                const uint32_t aoff = SWZ(wm * 32 + mt * 16 + a_ml, ks * 2 + a_c0);
                LDM4(ahf[0], ahf[1], ahf[2], ahf[3], ahb + aoff);
                LDM4(alf[0], alf[1], alf[2], alf[3], alb + aoff);
#pragma unroll
                for (int nt = 0; nt < 4; nt++) {
                    const int bi = (nt >> 1) * 4 + (nt & 1) * 2;
                    float* c = acc[mt][nt];
                    MMA16B(c, ahf, bhf[bi], bhf[bi + 1]);
                    MMA16B(c, ahf, blf[bi], blf[bi + 1]);
                    MMA16B(c, alf, bhf[bi], bhf[bi + 1]);
                }
            }
        }
    };

    issue(0); issue(1);
    for (int s2 = 0; s2 < S2; s2++) {
        CPWAIT1();
        __syncthreads();
        if (s2 + 2 < S2) issue(s2 + 2); else CPCOMMIT();
        const uint32_t stb = sb + (uint32_t)(s2 % 3) * STG64;
        compute32(stb);
        compute32(stb + STG32);
    }

    const int er = lane >> 2, ec = (lane & 3) * 2;
#pragma unroll
    for (int mt = 0; mt < 2; mt++) {
        const int m = m0 + wm * 32 + mt * 16 + er;
#pragma unroll
        for (int nt = 0; nt < 4; nt++) {
            const int n = n0 + wn * 32 + nt * 8 + ec;
            float bn0 = 0.f, bn1 = 0.f;
            if (BIAS == 1) { bn0 = bias[n]; bn1 = bias[n + 1]; }
            const float* c = acc[mt][nt];
            float v00 = c[0] + bn0, v01 = c[1] + bn1;
            float v10 = c[2] + bn0, v11 = c[3] + bn1;
            if (OUT == 0) {
                *reinterpret_cast<float2*>(Cf + (long)m * ldc + n) = make_float2(v00, v01);
                *reinterpret_cast<float2*>(Cf + (long)(m + 8) * ldc + n) = make_float2(v10, v11);
            } else {
                bf16 h0, l0, h1, l1;
                bsplit(v00, h0, l0); bsplit(v01, h1, l1);
                *reinterpret_cast<__nv_bfloat162*>(Ch + (long)m * ldc + n) = __halves2bfloat162(h0, h1);
                *reinterpret_cast<__nv_bfloat162*>(Cl + (long)m * ldc + n) = __halves2bfloat162(l0, l1);
                bsplit(v10, h0, l0); bsplit(v11, h1, l1);
                *reinterpret_cast<__nv_bfloat162*>(Ch + (long)(m + 8) * ldc + n) = __halves2bfloat162(h0, h1);
                *reinterpret_cast<__nv_bfloat162*>(Cl + (long)(m + 8) * ldc + n) = __halves2bfloat162(l0, l1);
            }
        }
    }
}

// ---------------------------------------------------------------------------
// Split core B (scores): MT=64, 256 thr (2x4 warps), BK=64, double buffer,
// smem = 98304 B -> 2 CTAs/SM with launch_bounds(256,2).
// ---------------------------------------------------------------------------
__device__ __forceinline__ void gemm_core_db(
    const bf16* __restrict__ Ah, const bf16* __restrict__ Al, int lda,
    const bf16* __restrict__ Bh, const bf16* __restrict__ Bl, int ldb,
    float* __restrict__ Cf, int ldc,
    int m0, int n0, int Keff)
{
    constexpr int ABY = 64 * 64;               // 4096
    constexpr int BBY = 8192;
    constexpr int STG32 = 2 * ABY + 2 * BBY;   // 24576
    constexpr int STG64 = 2 * STG32;           // 49152
    extern __shared__ uint16_t sm[];
    const uint32_t sb = smem_u32(sm);
    const int tid = threadIdx.x, lane = tid & 31, wrp = tid >> 5;
    const int wm = wrp >> 2, wn = wrp & 3;
    const int S2 = Keff >> 6;

    const int a_ml = (lane & 7) + ((lane >> 3) & 1) * 8;
    const int a_c0 = lane >> 4;
    const int b_nl = (lane & 7) + ((lane >> 4) << 3);
    const int b_c0 = (lane >> 3) & 1;

    const int row = tid >> 2, ch = tid & 3;
    const bf16* Aph = Ah + (long)(m0 + row) * lda + ch * 8;
    const bf16* Apl = Al + (long)(m0 + row) * lda + ch * 8;
    const bf16* Bph = Bh + (long)(n0 + row) * ldb + ch * 8;
    const bf16* Bpl = Bl + (long)(n0 + row) * ldb + ch * 8;
    const uint32_t swz = SWZ(row, ch);
    const uint32_t swz2 = SWZ(row + 64, ch);

    auto issue32 = [&](int k32, uint32_t db) {
        const int k0 = k32 << 5;
        CPA16(db + swz,                  Aph + k0);
        CPA16(db + ABY + swz,            Apl + k0);
        CPA16(db + 2 * ABY + swz,        Bph + k0);
        CPA16(db + 2 * ABY + swz2,       Bph + (long)64 * ldb + k0);
        CPA16(db + 2 * ABY + BBY + swz,  Bpl + k0);
        CPA16(db + 2 * ABY + BBY + swz2, Bpl + (long)64 * ldb + k0);
    };
    auto issue = [&](int s2) {
        const uint32_t db = sb + (uint32_t)(s2 & 1) * STG64;
        issue32(2 * s2, db);
        issue32(2 * s2 + 1, db + STG32);
        CPCOMMIT();
    };

    float acc[2][4][4] = {};

    auto compute32 = [&](uint32_t stb) {
        const uint32_t ahb = stb, alb = stb + ABY, bhb = stb + 2 * ABY, blb = bhb + BBY;
#pragma unroll
        for (int ks = 0; ks < 2; ks++) {
            uint32_t bhf[8], blf[8];
#pragma unroll
            for (int p = 0; p < 2; p++) {
                const uint32_t boff = SWZ(wn * 32 + p * 16 + b_nl, ks * 2 + b_c0);
                LDM4(bhf[p * 4 + 0], bhf[p * 4 + 1], bhf[p * 4 + 2], bhf[p * 4 + 3], bhb + boff);
                LDM4(blf[p * 4 + 0], blf[p * 4 + 1], blf[p * 4 + 2], blf[p * 4 + 3], blb + boff);
            }
#pragma unroll
            for (int mt = 0; mt < 2; mt++) {
                uint32_t ahf[4], alf[4];
                const uint32_t aoff = SWZ(wm * 32 + mt * 16 + a_ml, ks * 2 + a_c0);
                LDM4(ahf[0], ahf[1], ahf[2], ahf[3], ahb + aoff);
                LDM4(alf[0], alf[1], alf[2], alf[3], alb + aoff);
#pragma unroll
                for (int nt = 0; nt < 4; nt++) {
                    const int bi = (nt >> 1) * 4 + (nt & 1) * 2;
                    float* c = acc[mt][nt];
                    MMA16B(c, ahf, bhf[bi], bhf[bi + 1]);
                    MMA16B(c, ahf, blf[bi], blf[bi + 1]);
                    MMA16B(c, alf, bhf[bi], bhf[bi + 1]);
                }
            }
        }
    };

    issue(0);
    for (int s2 = 0; s2 < S2; s2++) {
        CPWAIT0();
        __syncthreads();
        if (s2 + 1 < S2) issue(s2 + 1);
        const uint32_t stb = sb + (uint32_t)(s2 & 1) * STG64;
        compute32(stb);
        compute32(stb + STG32);
        __syncthreads();
    }

    const int er = lane >> 2, ec = (lane & 3) * 2;
#pragma unroll
    for (int mt = 0; mt < 2; mt++) {
        const int m = m0 + wm * 32 + mt * 16 + er;
#pragma unroll
        for (int nt = 0; nt < 4; nt++) {
            const int n = n0 + wn * 32 + nt * 8 + ec;
            const float* c = acc[mt][nt];
            *reinterpret_cast<float2*>(Cf + (long)m * ldc + n) = make_float2(c[0], c[1]);
            *reinterpret_cast<float2*>(Cf + (long)(m + 8) * ldc + n) = make_float2(c[2], c[3]);
        }
    }
}

// ---------------------------------------------------------------------------
// fp16 single-pass core: 512 thr, 128x128 tile, BK=64, 3 stages. [R12 proven]
// ---------------------------------------------------------------------------
template <int BIAS, int OUT>
__device__ __forceinline__ void gemm_core_h(
    const __half* __restrict__ A, int lda, const __half* __restrict__ B, int ldb,
    const float* __restrict__ bias,
    float* __restrict__ Cf, __half* __restrict__ Chf, int ldc,
    int m0, int n0, int Keff)
{
    constexpr int BBY = 8192;
    constexpr int STG32 = 2 * BBY;
    constexpr int STG64 = 2 * STG32;
    extern __shared__ uint16_t sm[];
    const uint32_t sb = smem_u32(sm);
    const int tid = threadIdx.x, lane = tid & 31, wrp = tid >> 5;
    const int wm = wrp >> 2, wn = wrp & 3;
    const int S2 = Keff >> 6;

    const int a_ml = (lane & 7) + ((lane >> 3) & 1) * 8;
    const int a_c0 = lane >> 4;
    const int b_nl = (lane & 7) + ((lane >> 4) << 3);
    const int b_c0 = (lane >> 3) & 1;

    const int row = tid >> 2, ch = tid & 3;
    const __half* Ap = A + (long)(m0 + row) * lda + ch * 8;
    const __half* Bp = B + (long)(n0 + row) * ldb + ch * 8;
    const uint32_t swz = SWZ(row, ch);

    auto issue32 = [&](int k32, uint32_t db) {
        const int k0 = k32 << 5;
        CPA16(db + swz,       Ap + k0);
        CPA16(db + BBY + swz, Bp + k0);
    };
    auto issue = [&](int s2) {
        const uint32_t db = sb + (uint32_t)(s2 % 3) * STG64;
        issue32(2 * s2, db);
        issue32(2 * s2 + 1, db + STG32);
        CPCOMMIT();
    };

    float acc[2][4][4] = {};

    auto compute32 = [&](uint32_t stb) {
#pragma unroll
        for (int ks = 0; ks < 2; ks++) {
            uint32_t bhf[8];
#pragma unroll
            for (int p = 0; p < 2; p++) {
                const uint32_t boff = SWZ(wn * 32 + p * 16 + b_nl, ks * 2 + b_c0);
                LDM4(bhf[p * 4 + 0], bhf[p * 4 + 1], bhf[p * 4 + 2], bhf[p * 4 + 3], stb + BBY + boff);
            }
#pragma unroll
            for (int mt = 0; mt < 2; mt++) {
                uint32_t ahf[4];
                const uint32_t aoff = SWZ(wm * 32 + mt * 16 + a_ml, ks * 2 + a_c0);
                LDM4(ahf[0], ahf[1], ahf[2], ahf[3], stb + aoff);
#pragma unroll
                for (int nt = 0; nt < 4; nt++) {
                    const int bi = (nt >> 1) * 4 + (nt & 1) * 2;
                    MMA16H(acc[mt][nt], ahf, bhf[bi], bhf[bi + 1]);
                }
            }
        }
    };

    issue(0); issue(1);
    for (int s2 = 0; s2 < S2; s2++) {
        CPWAIT1();
        __syncthreads();
        if (s2 + 2 < S2) issue(s2 + 2); else CPCOMMIT();
        const uint32_t stb = sb + (uint32_t)(s2 % 3) * STG64;
        compute32(stb);
        compute32(stb + STG32);
    }

    const int er = lane >> 2, ec = (lane & 3) * 2;
#pragma unroll
    for (int mt = 0; mt < 2; mt++) {
        const int m = m0 + wm * 32 + mt * 16 + er;
        float bm0 = 0.f, bm8 = 0.f;
        if (BIAS == 2) { bm0 = bias[m]; bm8 = bias[m + 8]; }
#pragma unroll
        for (int nt = 0; nt < 4; nt++) {
            const int n = n0 + wn * 32 + nt * 8 + ec;
            float bn0 = 0.f, bn1 = 0.f;
            if (BIAS == 1) { bn0 = bias[n]; bn1 = bias[n + 1]; }
            const float* c = acc[mt][nt];
            float v00 = c[0] + bn0 + bm0, v01 = c[1] + bn1 + bm0;
            float v10 = c[2] + bn0 + bm8, v11 = c[3] + bn1 + bm8;
            if (OUT == 0) {
                *reinterpret_cast<float2*>(Cf + (long)m * ldc + n) = make_float2(v00, v01);
                *reinterpret_cast<float2*>(Cf + (long)(m + 8) * ldc + n) = make_float2(v10, v11);
            } else {
                *reinterpret_cast<__half2*>(Chf + (long)m * ldc + n) = __floats2half2_rn(v00, v01);
                *reinterpret_cast<__half2*>(Chf + (long)(m + 8) * ldc + n) = __floats2half2_rn(v10, v11);
            }
        }
    }
}

// ---------------------------------------------------------------------------
struct QKVP {
    const bf16 *xh, *xl;
    const __half *xf;
    const bf16 *qwh, *qwl, *kwh, *kwl;
    const __half *vwf;
    const float *qb, *kb, *vb;
    bf16 *qh, *ql, *kh, *kl;
    __half *vf;
};

__global__ void __launch_bounds__(512) qkv_kernel(QKVP p)
{
    const int bx = blockIdx.x, by = blockIdx.y, bz = blockIdx.z;
    if (bz == 0) {
        gemm_core<1, 1>(p.xh, p.xl, DD, p.qwh, p.qwl, DD, p.qb,
                        nullptr, p.qh, p.ql, DD, by * 128, bx * 128, DD);
    } else if (bz == 1) {
        gemm_core<1, 1>(p.xh, p.xl, DD, p.kwh, p.kwl, DD, p.kb,
                        nullptr, p.kh, p.kl, DD, by * 128, bx * 128, DD);
    } else {
        const int b = by >> 3, dt = by & 7;
        gemm_core_h<2, 1>(p.vwf, DD, p.xf + (long)b * MD, DD, p.vb,
                          nullptr, p.vf + (long)b * MD, TT, dt * 128, bx * 128, DD);
    }
}

__global__ void __launch_bounds__(256, 2) sc_kernel(const bf16* __restrict__ qh, const bf16* __restrict__ ql,
                                                    const bf16* __restrict__ kh, const bf16* __restrict__ kl,
                                                    float* __restrict__ a)
{
    const int bx = blockIdx.x, by = blockIdx.y, b = blockIdx.z;
    if (2 * bx > by) return;
    gemm_core_db(qh + (long)b * MD, ql + (long)b * MD, DD,
                 kh + (long)b * MD, kl + (long)b * MD, DD,
                 a + (long)b * AA, TT, by * 64, bx * 128, DD);
}

__global__ void __launch_bounds__(512, 2) av_kernel(const __half* __restrict__ wf,
                                                    const __half* __restrict__ vf,
                                                    float* __restrict__ o)
{
    const int bx = blockIdx.x, by = blockIdx.y, b = blockIdx.z;
    gemm_core_h<0, 0>(wf + (long)b * AA, TT, vf + (long)b * MD, TT, nullptr,
                      o + (long)b * MD, nullptr, DD,
                      by * 128, bx * 128, min(TT, by * 128 + 128));
}

__global__ void __launch_bounds__(512, 2) vocab_kernel(const __half* __restrict__ xn,
                                                       const __half* __restrict__ dwf,
                                                       const float* __restrict__ db,
                                                       float* __restrict__ out)
{
    gemm_core_h<1, 0>(xn, DD, dwf, DD, db, out, nullptr, VV,
                      blockIdx.x * 128, blockIdx.y * 128, DD);
}

// ---------------------------------------------------------------------------
__global__ void splitw_kernel(const float4* __restrict__ src, bf16* __restrict__ h,
                              bf16* __restrict__ l, int n4)
{
    int i = blockIdx.x * blockDim.x + threadIdx.x;
    if (i >= n4) return;
    float4 v = src[i];
    bf16 h0, l0, h1, l1, h2, l2, h3, l3;
    bsplit(v.x, h0, l0); bsplit(v.y, h1, l1); bsplit(v.z, h2, l2); bsplit(v.w, h3, l3);
    *reinterpret_cast<__nv_bfloat162*>(h + (long)i * 4)     = __halves2bfloat162(h0, h1);
    *reinterpret_cast<__nv_bfloat162*>(h + (long)i * 4 + 2) = __halves2bfloat162(h2, h3);
    *reinterpret_cast<__nv_bfloat162*>(l + (long)i * 4)     = __halves2bfloat162(l0, l1);
    *reinterpret_cast<__nv_bfloat162*>(l + (long)i * 4 + 2) = __halves2bfloat162(l2, l3);
}

__global__ void tohalf_kernel(const float4* __restrict__ src, __half* __restrict__ dst, int n4)
{
    int i = blockIdx.x * blockDim.x + threadIdx.x;
    if (i >= n4) return;
    float4 v = src[i];
    *reinterpret_cast<__half2*>(dst + (long)i * 4)     = __floats2half2_rn(v.x, v.y);
    *reinterpret_cast<__half2*>(dst + (long)i * 4 + 2) = __floats2half2_rn(v.z, v.w);
}

__device__ __forceinline__ void store_x3(float4 v, long off, float* X,
                                         bf16* xh, bf16* xl, __half* xf)
{
    if (X) *reinterpret_cast<float4*>(X + off) = v;
    bf16 h0, l0, h1, l1, h2, l2, h3, l3;
    bsplit(v.x, h0, l0); bsplit(v.y, h1, l1); bsplit(v.z, h2, l2); bsplit(v.w, h3, l3);
    *reinterpret_cast<__nv_bfloat162*>(xh + off)     = __halves2bfloat162(h0, h1);
    *reinterpret_cast<__nv_bfloat162*>(xh + off + 2) = __halves2bfloat162(h2, h3);
    *reinterpret_cast<__nv_bfloat162*>(xl + off)     = __halves2bfloat162(l0, l1);
    *reinterpret_cast<__nv_bfloat162*>(xl + off + 2) = __halves2bfloat162(l2, l3);
    *reinterpret_cast<__half2*>(xf + off)     = __floats2half2_rn(v.x, v.y);
    *reinterpret_cast<__half2*>(xf + off + 2) = __floats2half2_rn(v.z, v.w);
}

__global__ void embed_pe_kernel(const int* __restrict__ src, const float* __restrict__ pe,
                                const float* __restrict__ embed, float* __restrict__ x,
                                bf16* __restrict__ xh, bf16* __restrict__ xl, __half* __restrict__ xf)
{
    int row = blockIdx.x, b = row >> 10;
    long tok = src[row];
    const float4* e = reinterpret_cast<const float4*>(embed + tok * (long)DD);
    const float4* p = reinterpret_cast<const float4*>(pe + (long)b * DD);
    int i = threadIdx.x;
    float4 ev = e[i], pv = p[i];
    float4 v = make_float4(ev.x + pv.x, ev.y + pv.y, ev.z + pv.z, ev.w + pv.w);
    store_x3(v, (long)row * DD + i * 4, x, xh, xl, xf);
}

__global__ void softmax_kernel(const float* __restrict__ A, __half* __restrict__ Wf)
{
    int t = blockIdx.x, b = blockIdx.y;
    const float* row = A + ((long)b * TT + t) * TT;
    __half* wf = Wf + ((long)b * TT + t) * TT;
    int n = t + 1, i = threadIdx.x;
    __shared__ float red[256];
    __shared__ float rowe[TT];
    float m = -1e30f;
    for (int s = i; s < n; s += 256) m = fmaxf(m, row[s]);
    red[i] = m; __syncthreads();
    for (int st = 128; st > 0; st >>= 1) { if (i < st) red[i] = fmaxf(red[i], red[i + st]); __syncthreads(); }
    m = red[0]; __syncthreads();
    float sum = 0.f;
    for (int s = i; s < n; s += 256) { float e = expf(row[s] - m); rowe[s] = e; sum += e; }
    red[i] = sum; __syncthreads();
    for (int st = 128; st > 0; st >>= 1) { if (i < st) red[i] += red[i + st]; __syncthreads(); }
    float inv = 1.0f / red[0];
    for (int s = i; s < TT; s += 256)
        wf[s] = (s < n) ? __float2half_rn(rowe[s] * inv) : __float2half_rn(0.f);
}

__global__ void ln_res_kernel(const float* __restrict__ O, const float* __restrict__ w,
                              const float* __restrict__ bb, float* __restrict__ X,
                              bf16* __restrict__ xh, bf16* __restrict__ xl, __half* __restrict__ xf)
{
    int row = blockIdx.x, i = threadIdx.x;
    const float4 o = reinterpret_cast<const float4*>(O + (long)row * DD)[i];
    float4* x4 = reinterpret_cast<float4*>(X + (long)row * DD);
    __shared__ float red[256];
    red[i] = o.x + o.y + o.z + o.w; __syncthreads();
    for (int st = 128; st > 0; st >>= 1) { if (i < st) red[i] += red[i + st]; __syncthreads(); }
    float mu = red[0] * (1.0f / DD); __syncthreads();
    float dx = o.x - mu, dy = o.y - mu, dz = o.z - mu, dw_ = o.w - mu;
    red[i] = dx * dx + dy * dy + dz * dz + dw_ * dw_; __syncthreads();
    for (int st = 128; st > 0; st >>= 1) { if (i < st) red[i] += red[i + st]; __syncthreads(); }
    float rstd = rsqrtf(red[0] * (1.0f / DD) + 1e-6f);
    float4 wv = reinterpret_cast<const float4*>(w)[i];
    float4 bv = reinterpret_cast<const float4*>(bb)[i];
    float4 xv = x4[i];
    xv.x += dx * rstd * wv.x + bv.x;
    xv.y += dy * rstd * wv.y + bv.y;
    xv.z += dz * rstd * wv.z + bv.z;
    xv.w += dw_ * rstd * wv.w + bv.w;
    x4[i] = xv;
    store_x3(xv, (long)row * DD + i * 4, nullptr, xh, xl, xf);
}

__global__ void final_ln_kernel(const float* __restrict__ X, const float* __restrict__ fw,
                                const float* __restrict__ fb, __half* __restrict__ Y)
{
    int row = blockIdx.x, i = threadIdx.x;
    const float4 x = reinterpret_cast<const float4*>(X + (long)row * DD)[i];
    __shared__ float red[256];
    red[i] = x.x + x.y + x.z + x.w; __syncthreads();
    for (int st = 128; st > 0; st >>= 1) { if (i < st) red[i] += red[i + st]; __syncthreads(); }
    float mu = red[0] * (1.0f / DD); __syncthreads();
    float dx = x.x - mu, dy = x.y - mu, dz = x.z - mu, dw_ = x.w - mu;
    red[i] = dx * dx + dy * dy + dz * dz + dw_ * dw_; __syncthreads();
    for (int st = 128; st > 0; st >>= 1) { if (i < st) red[i] += red[i + st]; __syncthreads(); }
    float rstd = rsqrtf(red[0] * (1.0f / DD) + 1e-5f);
    float4 wv = reinterpret_cast<const float4*>(fw)[i];
    float4 bv = reinterpret_cast<const float4*>(fb)[i];
    long off = (long)row * DD + i * 4;
    *reinterpret_cast<__half2*>(Y + off)     = __floats2half2_rn(dx * rstd * wv.x + bv.x, dy * rstd * wv.y + bv.y);
    *reinterpret_cast<__half2*>(Y + off + 2) = __floats2half2_rn(dz * rstd * wv.z + bv.z, dw_ * rstd * wv.w + bv.w);
}

// ---------------------------------------------------------------------------
extern "C" void kernel_launch(void* const* d_in, const int* in_sizes, int n_in,
                              void* d_out, int out_size)
{
    const int*   src = (const int*)d_in[0];
    const float* pe  = (const float*)d_in[1];
    const float* emb = (const float*)d_in[2];
    const float* qw  = (const float*)d_in[3];
    const float* qb  = (const float*)d_in[4];
    const float* kw  = (const float*)d_in[5];
    const float* kb  = (const float*)d_in[6];
    const float* vw  = (const float*)d_in[7];
    const float* vb  = (const float*)d_in[8];
    const float* lnw = (const float*)d_in[9];
    const float* lnb = (const float*)d_in[10];
    const float* fw  = (const float*)d_in[11];
    const float* fb  = (const float*)d_in[12];
    const float* dw  = (const float*)d_in[13];
    const float* db  = (const float*)d_in[14];
    float* out = (float*)d_out;

#define GA(sym, var) void* var##_; cudaGetSymbolAddress(&var##_, sym)
    GA(g_x, x);  GA(g_a, a);  GA(g_o, o);
    GA(g_xh, xh); GA(g_xl, xl); GA(g_xf, xf);
    GA(g_qh, qh); GA(g_ql, ql); GA(g_kh, kh); GA(g_kl, kl);
    GA(g_vf, vf); GA(g_wf, wf);
    GA(g_qwh, qwh); GA(g_qwl, qwl); GA(g_kwh, kwh); GA(g_kwl, kwl);
    GA(g_vwf, vwf); GA(g_dwf, dwf); GA(g_xnf, xnf);
#undef GA

    const int SMB = 3 * 2 * (2 * 8192 + 2 * 8192);   // 196608 (split MT=128, 3 stages)
    const int SMS = 2 * 49152;                       // 98304  (split MT=64 double buffer)
    const int SMH = 3 * 2 * (2 * 8192);              // 98304  (fp16, 3 stages)
    cudaFuncSetAttribute(qkv_kernel,   cudaFuncAttributeMaxDynamicSharedMemorySize, SMB);
    cudaFuncSetAttribute(sc_kernel,    cudaFuncAttributeMaxDynamicSharedMemorySize, SMS);
    cudaFuncSetAttribute(av_kernel,    cudaFuncAttributeMaxDynamicSharedMemorySize, SMH);
    cudaFuncSetAttribute(vocab_kernel, cudaFuncAttributeMaxDynamicSharedMemorySize, SMH);

    {
        const int n4w = LL * DD * DD / 4;
        splitw_kernel<<<(n4w + 511) / 512, 512>>>((const float4*)qw, (bf16*)qwh_, (bf16*)qwl_, n4w);
        splitw_kernel<<<(n4w + 511) / 512, 512>>>((const float4*)kw, (bf16*)kwh_, (bf16*)kwl_, n4w);
        tohalf_kernel<<<(n4w + 511) / 512, 512>>>((const float4*)vw, (__half*)vwf_, n4w);
        const int n4d = VV * DD / 4;
        tohalf_kernel<<<(n4d + 511) / 512, 512>>>((const float4*)dw, (__half*)dwf_, n4d);
    }

    embed_pe_kernel<<<BB * TT, 256>>>(src, pe, emb, (float*)x_, (bf16*)xh_, (bf16*)xl_, (__half*)xf_);

    dim3 gqkv(DD / 128, (BB * TT) / 128, 3);   // 8 x 16 x 3
    dim3 gsc(TT / 128, TT / 64, BB);           // 8 x 16 x 2 (causal skip)
    dim3 gav(TT / 128, TT / 128, BB);
    for (int l = 0; l < LL; l++) {
        const long wo = (long)l * DD * DD;
        QKVP p;
        p.xh = (const bf16*)xh_; p.xl = (const bf16*)xl_; p.xf = (const __half*)xf_;
        p.qwh = (const bf16*)qwh_ + wo; p.qwl = (const bf16*)qwl_ + wo;
        p.kwh = (const bf16*)kwh_ + wo; p.kwl = (const bf16*)kwl_ + wo;
        p.vwf = (const __half*)vwf_ + wo;
        p.qb = qb + l * DD; p.kb = kb + l * DD; p.vb = vb + l * DD;
        p.qh = (bf16*)qh_; p.ql = (bf16*)ql_;
        p.kh = (bf16*)kh_; p.kl = (bf16*)kl_;
        p.vf = (__half*)vf_;
        qkv_kernel<<<gqkv, 512, SMB>>>(p);
        sc_kernel<<<gsc, 256, SMS>>>((const bf16*)qh_, (const bf16*)ql_,
                                     (const bf16*)kh_, (const bf16*)kl_, (float*)a_);
        softmax_kernel<<<dim3(TT, BB), 256>>>((const float*)a_, (__half*)wf_);
        av_kernel<<<gav, 512, SMH>>>((const __half*)wf_, (const __half*)vf_, (float*)o_);
        ln_res_kernel<<<BB * TT, 256>>>((const float*)o_, lnw + l * DD, lnb + l * DD,
                                        (float*)x_, (bf16*)xh_, (bf16*)xl_, (__half*)xf_);
    }

    final_ln_kernel<<<BB * TT, 256>>>((const float*)x_, fw, fb, (__half*)xnf_);
    dim3 gf((BB * TT) / 128, VV / 128);
    vocab_kernel<<<gf, 512, SMH>>>((const __half*)xnf_, (const __half*)dwf_, db, out);
}

// round 15
// speedup vs baseline: 1.0761x; 1.0761x over previous
#include <cuda_runtime.h>
#include <cuda_bf16.h>
#include <cuda_fp16.h>
#include <cstdint>

#define BB 2
#define TT 1024
#define DD 1024
#define VV 32000
#define LL 8
#define MD (TT * DD)
#define AA (TT * TT)

typedef __nv_bfloat16 bf16;

// fp32 masters
__device__ float g_x[BB * MD];
__device__ float g_a[BB * AA];
__device__ float g_o[BB * MD];
// split bf16 operands (accurate path: x, Q, K, weights qw/kw)
__device__ bf16 g_xh[BB * MD], g_xl[BB * MD];
__device__ bf16 g_qh[BB * MD], g_ql[BB * MD];
__device__ bf16 g_kh[BB * MD], g_kl[BB * MD];
__device__ bf16 g_qwh[LL * DD * DD], g_qwl[LL * DD * DD];
__device__ bf16 g_kwh[LL * DD * DD], g_kwl[LL * DD * DD];
// single fp16 operands (relaxed path: V, w, vw, dw, xn, x-as-fp16)
__device__ __half g_xf[BB * MD];
__device__ __half g_vf[BB * MD];          // V^T [b][d][t]
__device__ __half g_wf[BB * AA];
__device__ __half g_vwf[LL * DD * DD];
__device__ __half g_dwf[VV * DD];
__device__ __half g_xnf[BB * MD];

#define NSTAGE 3
// 64B rows + XOR swizzle: chunk c (16B) of row r at r*64 + (c ^ ((r>>1)&3))*16.
// Conflict-free for ldmatrix (8 rows cover all 32 banks exactly once).
#define SWZ(r, c) ((((uint32_t)(r)) << 6) + ((((c) ^ (((r) >> 1) & 3))) << 4))

__device__ __forceinline__ uint32_t smem_u32(const void* p) {
    uint32_t a;
    asm("{ .reg .u64 t; cvta.to.shared.u64 t, %1; cvt.u32.u64 %0, t; }" : "=r"(a) : "l"(p));
    return a;
}
#define LDM4(r0, r1, r2, r3, ad) \
    asm volatile("ldmatrix.sync.aligned.m8n8.x4.shared.b16 {%0,%1,%2,%3},[%4];" \
                 : "=r"(r0), "=r"(r1), "=r"(r2), "=r"(r3) : "r"(ad))
#define MMA16B(c, a, b0_, b1_) \
    asm volatile("mma.sync.aligned.m16n8k16.row.col.f32.bf16.bf16.f32 " \
                 "{%0,%1,%2,%3},{%4,%5,%6,%7},{%8,%9},{%0,%1,%2,%3};" \
                 : "+f"((c)[0]), "+f"((c)[1]), "+f"((c)[2]), "+f"((c)[3]) \
                 : "r"((a)[0]), "r"((a)[1]), "r"((a)[2]), "r"((a)[3]), "r"(b0_), "r"(b1_))
#define MMA16H(c, a, b0_, b1_) \
    asm volatile("mma.sync.aligned.m16n8k16.row.col.f32.f16.f16.f32 " \
                 "{%0,%1,%2,%3},{%4,%5,%6,%7},{%8,%9},{%0,%1,%2,%3};" \
                 : "+f"((c)[0]), "+f"((c)[1]), "+f"((c)[2]), "+f"((c)[3]) \
                 : "r"((a)[0]), "r"((a)[1]), "r"((a)[2]), "r"((a)[3]), "r"(b0_), "r"(b1_))
#define CPA16(d, s) asm volatile("cp.async.cg.shared.global [%0], [%1], 16;" :: "r"(d), "l"(s))
#define CPCOMMIT()  asm volatile("cp.async.commit_group;" ::: "memory")
#define CPWAIT1()   asm volatile("cp.async.wait_group 1;" ::: "memory")

__device__ __forceinline__ void bsplit(float v, bf16& h, bf16& l) {
    h = __float2bfloat16_rn(v);
    l = __float2bfloat16_rn(v - __bfloat162float(h));
}

// ---------------------------------------------------------------------------
// bf16 3-term split GEMM core. MT=128: 512 thr (4x4 warps of 32x32).
// MT=64: 256 thr (2x4 warps). N tile 128. Stages of BK=64 (two 32-K
// sub-buffers), NSTAGE=3, loads issued 2 stages ahead BEFORE compute.
// BIAS: 0 none, 1 per-N.  OUT: 0 fp32 Cf, 1 bf16 hi/lo Ch/Cl.
// ---------------------------------------------------------------------------
template <int MT, int BIAS, int OUT>
__device__ __forceinline__ void gemm_core(
    const bf16* __restrict__ Ah, const bf16* __restrict__ Al, int lda,
    const bf16* __restrict__ Bh, const bf16* __restrict__ Bl, int ldb,
    const float* __restrict__ bias,
    float* __restrict__ Cf, bf16* __restrict__ Ch, bf16* __restrict__ Cl, int ldc,
    int m0, int n0, int Keff)
{
    constexpr int ABY = MT * 64;
    constexpr int BBY = 8192;
    constexpr int STG32 = 2 * ABY + 2 * BBY;
    constexpr int STG64 = 2 * STG32;
    extern __shared__ uint16_t sm[];
    const uint32_t sb = smem_u32(sm);
    const int tid = threadIdx.x, lane = tid & 31, wrp = tid >> 5;
    const int wm = wrp >> 2, wn = wrp & 3;
    const int S2 = Keff >> 6;

    const int a_ml = (lane & 7) + ((lane >> 3) & 1) * 8;
    const int a_c0 = lane >> 4;
    const int b_nl = (lane & 7) + ((lane >> 4) << 3);
    const int b_c0 = (lane >> 3) & 1;

    const int row = tid >> 2, ch = tid & 3;
    const bf16* Aph = Ah + (long)(m0 + row) * lda + ch * 8;
    const bf16* Apl = Al + (long)(m0 + row) * lda + ch * 8;
    const bf16* Bph = Bh + (long)(n0 + row) * ldb + ch * 8;
    const bf16* Bpl = Bl + (long)(n0 + row) * ldb + ch * 8;
    const uint32_t swz = SWZ(row, ch);
    const uint32_t swz2 = SWZ(row + 64, ch);

    auto issue32 = [&](int k32, uint32_t db) {
        const int k0 = k32 << 5;
        CPA16(db + swz,                 Aph + k0);
        CPA16(db + ABY + swz,           Apl + k0);
        CPA16(db + 2 * ABY + swz,       Bph + k0);
        CPA16(db + 2 * ABY + BBY + swz, Bpl + k0);
        if (MT == 64) {
            CPA16(db + 2 * ABY + swz2,       Bph + (long)64 * ldb + k0);
            CPA16(db + 2 * ABY + BBY + swz2, Bpl + (long)64 * ldb + k0);
        }
    };
    auto issue = [&](int s2) {
        const uint32_t db = sb + (uint32_t)(s2 % NSTAGE) * STG64;
        issue32(2 * s2, db);
        issue32(2 * s2 + 1, db + STG32);
        CPCOMMIT();
    };

    float acc[2][4][4] = {};

    auto compute32 = [&](uint32_t stb) {
        const uint32_t ahb = stb, alb = stb + ABY, bhb = stb + 2 * ABY, blb = bhb + BBY;
#pragma unroll
        for (int ks = 0; ks < 2; ks++) {
            uint32_t bhf[8], blf[8];
#pragma unroll
            for (int p = 0; p < 2; p++) {
                const uint32_t boff = SWZ(wn * 32 + p * 16 + b_nl, ks * 2 + b_c0);
                LDM4(bhf[p * 4 + 0], bhf[p * 4 + 1], bhf[p * 4 + 2], bhf[p * 4 + 3], bhb + boff);
                LDM4(blf[p * 4 + 0], blf[p * 4 + 1], blf[p * 4 + 2], blf[p * 4 + 3], blb + boff);
            }
#pragma unroll
            for (int mt = 0; mt < 2; mt++) {
                uint32_t ahf[4], alf[4];
                const uint32_t aoff = SWZ(wm * 32 + mt * 16 + a_ml, ks * 2 + a_c0);
                LDM4(ahf[0], ahf[1], ahf[2], ahf[3], ahb + aoff);
                LDM4(alf[0], alf[1], alf[2], alf[3], alb + aoff);
#pragma unroll
                for (int nt = 0; nt < 4; nt++) {
                    const int bi = (nt >> 1) * 4 + (nt & 1) * 2;
                    float* c = acc[mt][nt];
                    MMA16B(c, ahf, bhf[bi], bhf[bi + 1]);
                    MMA16B(c, ahf, blf[bi], blf[bi + 1]);
                    MMA16B(c, alf, bhf[bi], bhf[bi + 1]);
                }
            }
        }
    };

    issue(0); issue(1);
    for (int s2 = 0; s2 < S2; s2++) {
        CPWAIT1();
        __syncthreads();
        if (s2 + 2 < S2) issue(s2 + 2); else CPCOMMIT();
        const uint32_t stb = sb + (uint32_t)(s2 % NSTAGE) * STG64;
        compute32(stb);
        compute32(stb + STG32);
    }

    const int er = lane >> 2, ec = (lane & 3) * 2;
#pragma unroll
    for (int mt = 0; mt < 2; mt++) {
        const int m = m0 + wm * 32 + mt * 16 + er;
#pragma unroll
        for (int nt = 0; nt < 4; nt++) {
            const int n = n0 + wn * 32 + nt * 8 + ec;
            float bn0 = 0.f, bn1 = 0.f;
            if (BIAS == 1) { bn0 = bias[n]; bn1 = bias[n + 1]; }
            const float* c = acc[mt][nt];
            float v00 = c[0] + bn0, v01 = c[1] + bn1;
            float v10 = c[2] + bn0, v11 = c[3] + bn1;
            if (OUT == 0) {
                *reinterpret_cast<float2*>(Cf + (long)m * ldc + n) = make_float2(v00, v01);
                *reinterpret_cast<float2*>(Cf + (long)(m + 8) * ldc + n) = make_float2(v10, v11);
            } else {
                bf16 h0, l0, h1, l1;
                bsplit(v00, h0, l0); bsplit(v01, h1, l1);
                *reinterpret_cast<__nv_bfloat162*>(Ch + (long)m * ldc + n) = __halves2bfloat162(h0, h1);
                *reinterpret_cast<__nv_bfloat162*>(Cl + (long)m * ldc + n) = __halves2bfloat162(l0, l1);
                bsplit(v10, h0, l0); bsplit(v11, h1, l1);
                *reinterpret_cast<__nv_bfloat162*>(Ch + (long)(m + 8) * ldc + n) = __halves2bfloat162(h0, h1);
                *reinterpret_cast<__nv_bfloat162*>(Cl + (long)(m + 8) * ldc + n) = __halves2bfloat162(l0, l1);
            }
        }
    }
}

// ---------------------------------------------------------------------------
// fp16 single-pass core: 512 thr, 128x128 tile, BK=64 stages, issue-ahead.
// BIAS: 0 none, 1 per-N, 2 per-M.  OUT: 0 fp32 Cf, 1 fp16 Chf.
// ---------------------------------------------------------------------------
template <int BIAS, int OUT>
__device__ __forceinline__ void gemm_core_h(
    const __half* __restrict__ A, int lda, const __half* __restrict__ B, int ldb,
    const float* __restrict__ bias,
    float* __restrict__ Cf, __half* __restrict__ Chf, int ldc,
    int m0, int n0, int Keff)
{
    constexpr int BBY = 8192;
    constexpr int STG32 = 2 * BBY;
    constexpr int STG64 = 2 * STG32;
    extern __shared__ uint16_t sm[];
    const uint32_t sb = smem_u32(sm);
    const int tid = threadIdx.x, lane = tid & 31, wrp = tid >> 5;
    const int wm = wrp >> 2, wn = wrp & 3;
    const int S2 = Keff >> 6;

    const int a_ml = (lane & 7) + ((lane >> 3) & 1) * 8;
    const int a_c0 = lane >> 4;
    const int b_nl = (lane & 7) + ((lane >> 4) << 3);
    const int b_c0 = (lane >> 3) & 1;

    const int row = tid >> 2, ch = tid & 3;
    const __half* Ap = A + (long)(m0 + row) * lda + ch * 8;
    const __half* Bp = B + (long)(n0 + row) * ldb + ch * 8;
    const uint32_t swz = SWZ(row, ch);

    auto issue32 = [&](int k32, uint32_t db) {
        const int k0 = k32 << 5;
        CPA16(db + swz,       Ap + k0);
        CPA16(db + BBY + swz, Bp + k0);
    };
    auto issue = [&](int s2) {
        const uint32_t db = sb + (uint32_t)(s2 % NSTAGE) * STG64;
        issue32(2 * s2, db);
        issue32(2 * s2 + 1, db + STG32);
        CPCOMMIT();
    };

    float acc[2][4][4] = {};

    auto compute32 = [&](uint32_t stb) {
#pragma unroll
        for (int ks = 0; ks < 2; ks++) {
            uint32_t bhf[8];
#pragma unroll
            for (int p = 0; p < 2; p++) {
                const uint32_t boff = SWZ(wn * 32 + p * 16 + b_nl, ks * 2 + b_c0);
                LDM4(bhf[p * 4 + 0], bhf[p * 4 + 1], bhf[p * 4 + 2], bhf[p * 4 + 3], stb + BBY + boff);
            }
#pragma unroll
            for (int mt = 0; mt < 2; mt++) {
                uint32_t ahf[4];
                const uint32_t aoff = SWZ(wm * 32 + mt * 16 + a_ml, ks * 2 + a_c0);
                LDM4(ahf[0], ahf[1], ahf[2], ahf[3], stb + aoff);
#pragma unroll
                for (int nt = 0; nt < 4; nt++) {
                    const int bi = (nt >> 1) * 4 + (nt & 1) * 2;
                    MMA16H(acc[mt][nt], ahf, bhf[bi], bhf[bi + 1]);
                }
            }
        }
    };

    issue(0); issue(1);
    for (int s2 = 0; s2 < S2; s2++) {
        CPWAIT1();
        __syncthreads();
        if (s2 + 2 < S2) issue(s2 + 2); else CPCOMMIT();
        const uint32_t stb = sb + (uint32_t)(s2 % NSTAGE) * STG64;
        compute32(stb);
        compute32(stb + STG32);
    }

    const int er = lane >> 2, ec = (lane & 3) * 2;
#pragma unroll
    for (int mt = 0; mt < 2; mt++) {
        const int m = m0 + wm * 32 + mt * 16 + er;
        float bm0 = 0.f, bm8 = 0.f;
        if (BIAS == 2) { bm0 = bias[m]; bm8 = bias[m + 8]; }
#pragma unroll
        for (int nt = 0; nt < 4; nt++) {
            const int n = n0 + wn * 32 + nt * 8 + ec;
            float bn0 = 0.f, bn1 = 0.f;
            if (BIAS == 1) { bn0 = bias[n]; bn1 = bias[n + 1]; }
            const float* c = acc[mt][nt];
            float v00 = c[0] + bn0 + bm0, v01 = c[1] + bn1 + bm0;
            float v10 = c[2] + bn0 + bm8, v11 = c[3] + bn1 + bm8;
            if (OUT == 0) {
                *reinterpret_cast<float2*>(Cf + (long)m * ldc + n) = make_float2(v00, v01);
                *reinterpret_cast<float2*>(Cf + (long)(m + 8) * ldc + n) = make_float2(v10, v11);
            } else {
                *reinterpret_cast<__half2*>(Chf + (long)m * ldc + n) = __floats2half2_rn(v00, v01);
                *reinterpret_cast<__half2*>(Chf + (long)(m + 8) * ldc + n) = __floats2half2_rn(v10, v11);
            }
        }
    }
}

// ---------------------------------------------------------------------------
// Kernel wrappers
// ---------------------------------------------------------------------------
struct QKVP {
    const bf16 *xh, *xl;
    const __half *xf;
    const bf16 *qwh, *qwl, *kwh, *kwl;
    const __half *vwf;
    const float *qb, *kb, *vb;
    bf16 *qh, *ql, *kh, *kl;
    __half *vf;
};

__global__ void __launch_bounds__(512) qkv_kernel(QKVP p)
{
    const int bx = blockIdx.x, by = blockIdx.y, bz = blockIdx.z;
    if (bz == 0) {
        gemm_core<128, 1, 1>(p.xh, p.xl, DD, p.qwh, p.qwl, DD, p.qb,
                             nullptr, p.qh, p.ql, DD, by * 128, bx * 128, DD);
    } else if (bz == 1) {
        gemm_core<128, 1, 1>(p.xh, p.xl, DD, p.kwh, p.kwl, DD, p.kb,
                             nullptr, p.kh, p.kl, DD, by * 128, bx * 128, DD);
    } else {
        // V^T = vw @ x^T, single fp16, per-M bias, fp16 out
        const int b = by >> 3, dt = by & 7;
        gemm_core_h<2, 1>(p.vwf, DD, p.xf + (long)b * MD, DD, p.vb,
                          nullptr, p.vf + (long)b * MD, TT, dt * 128, bx * 128, DD);
    }
}

// scores: split bf16, M-tile 64 (256 thr), causal skip
__global__ void __launch_bounds__(256) sc_kernel(const bf16* __restrict__ qh, const bf16* __restrict__ ql,
                                                 const bf16* __restrict__ kh, const bf16* __restrict__ kl,
                                                 float* __restrict__ a)
{
    const int bx = blockIdx.x, by = blockIdx.y, b = blockIdx.z;
    if (2 * bx > by) return;
    gemm_core<64, 0, 0>(qh + (long)b * MD, ql + (long)b * MD, DD,
                        kh + (long)b * MD, kl + (long)b * MD, DD, nullptr,
                        a + (long)b * AA, nullptr, nullptr, TT, by * 64, bx * 128, DD);
}

// o = w @ V, single fp16, K-limited
__global__ void __launch_bounds__(512, 2) av_kernel(const __half* __restrict__ wf,
                                                    const __half* __restrict__ vf,
                                                    float* __restrict__ o)
{
    const int bx = blockIdx.x, by = blockIdx.y, b = blockIdx.z;
    gemm_core_h<0, 0>(wf + (long)b * AA, TT, vf + (long)b * MD, TT, nullptr,
                      o + (long)b * MD, nullptr, DD,
                      by * 128, bx * 128, min(TT, by * 128 + 128));
}

// vocab: grid x = M tiles (fast) so consecutive CTAs share the dw tile in L2
__global__ void __launch_bounds__(512, 2) vocab_kernel(const __half* __restrict__ xn,
                                                       const __half* __restrict__ dwf,
                                                       const float* __restrict__ db,
                                                       float* __restrict__ out)
{
    gemm_core_h<1, 0>(xn, DD, dwf, DD, db, out, nullptr, VV,
                      blockIdx.x * 128, blockIdx.y * 128, DD);
}

// ---------------------------------------------------------------------------
// Converters + elementwise
// ---------------------------------------------------------------------------
__global__ void splitw_kernel(const float4* __restrict__ src, bf16* __restrict__ h,
                              bf16* __restrict__ l, int n4)
{
    int i = blockIdx.x * blockDim.x + threadIdx.x;
    if (i >= n4) return;
    float4 v = src[i];
    bf16 h0, l0, h1, l1, h2, l2, h3, l3;
    bsplit(v.x, h0, l0); bsplit(v.y, h1, l1); bsplit(v.z, h2, l2); bsplit(v.w, h3, l3);
    *reinterpret_cast<__nv_bfloat162*>(h + (long)i * 4)     = __halves2bfloat162(h0, h1);
    *reinterpret_cast<__nv_bfloat162*>(h + (long)i * 4 + 2) = __halves2bfloat162(h2, h3);
    *reinterpret_cast<__nv_bfloat162*>(l + (long)i * 4)     = __halves2bfloat162(l0, l1);
    *reinterpret_cast<__nv_bfloat162*>(l + (long)i * 4 + 2) = __halves2bfloat162(l2, l3);
}

__global__ void tohalf_kernel(const float4* __restrict__ src, __half* __restrict__ dst, int n4)
{
    int i = blockIdx.x * blockDim.x + threadIdx.x;
    if (i >= n4) return;
    float4 v = src[i];
    *reinterpret_cast<__half2*>(dst + (long)i * 4)     = __floats2half2_rn(v.x, v.y);
    *reinterpret_cast<__half2*>(dst + (long)i * 4 + 2) = __floats2half2_rn(v.z, v.w);
}

__device__ __forceinline__ void store_x3(float4 v, long off, float* X,
                                         bf16* xh, bf16* xl, __half* xf)
{
    if (X) *reinterpret_cast<float4*>(X + off) = v;
    bf16 h0, l0, h1, l1, h2, l2, h3, l3;
    bsplit(v.x, h0, l0); bsplit(v.y, h1, l1); bsplit(v.z, h2, l2); bsplit(v.w, h3, l3);
    *reinterpret_cast<__nv_bfloat162*>(xh + off)     = __halves2bfloat162(h0, h1);
    *reinterpret_cast<__nv_bfloat162*>(xh + off + 2) = __halves2bfloat162(h2, h3);
    *reinterpret_cast<__nv_bfloat162*>(xl + off)     = __halves2bfloat162(l0, l1);
    *reinterpret_cast<__nv_bfloat162*>(xl + off + 2) = __halves2bfloat162(l2, l3);
    *reinterpret_cast<__half2*>(xf + off)     = __floats2half2_rn(v.x, v.y);
    *reinterpret_cast<__half2*>(xf + off + 2) = __floats2half2_rn(v.z, v.w);
}

__global__ void embed_pe_kernel(const int* __restrict__ src, const float* __restrict__ pe,
                                const float* __restrict__ embed, float* __restrict__ x,
                                bf16* __restrict__ xh, bf16* __restrict__ xl, __half* __restrict__ xf)
{
    int row = blockIdx.x, b = row >> 10;
    long tok = src[row];
    const float4* e = reinterpret_cast<const float4*>(embed + tok * (long)DD);
    const float4* p = reinterpret_cast<const float4*>(pe + (long)b * DD);
    int i = threadIdx.x;
    float4 ev = e[i], pv = p[i];
    float4 v = make_float4(ev.x + pv.x, ev.y + pv.y, ev.z + pv.z, ev.w + pv.w);
    store_x3(v, (long)row * DD + i * 4, x, xh, xl, xf);
}

__global__ void softmax_kernel(const float* __restrict__ A, __half* __restrict__ Wf)
{
    int t = blockIdx.x, b = blockIdx.y;
    const float* row = A + ((long)b * TT + t) * TT;
    __half* wf = Wf + ((long)b * TT + t) * TT;
    int n = t + 1, i = threadIdx.x;
    __shared__ float red[256];
    __shared__ float rowe[TT];
    float m = -1e30f;
    for (int s = i; s < n; s += 256) m = fmaxf(m, row[s]);
    red[i] = m; __syncthreads();
    for (int st = 128; st > 0; st >>= 1) { if (i < st) red[i] = fmaxf(red[i], red[i + st]); __syncthreads(); }
    m = red[0]; __syncthreads();
    float sum = 0.f;
    for (int s = i; s < n; s += 256) { float e = expf(row[s] - m); rowe[s] = e; sum += e; }
    red[i] = sum; __syncthreads();
    for (int st = 128; st > 0; st >>= 1) { if (i < st) red[i] += red[i + st]; __syncthreads(); }
    float inv = 1.0f / red[0];
    for (int s = i; s < TT; s += 256)
        wf[s] = (s < n) ? __float2half_rn(rowe[s] * inv) : __float2half_rn(0.f);
}

__global__ void ln_res_kernel(const float* __restrict__ O, const float* __restrict__ w,
                              const float* __restrict__ bb, float* __restrict__ X,
                              bf16* __restrict__ xh, bf16* __restrict__ xl, __half* __restrict__ xf)
{
    int row = blockIdx.x, i = threadIdx.x;
    const float4 o = reinterpret_cast<const float4*>(O + (long)row * DD)[i];
    float4* x4 = reinterpret_cast<float4*>(X + (long)row * DD);
    __shared__ float red[256];
    red[i] = o.x + o.y + o.z + o.w; __syncthreads();
    for (int st = 128; st > 0; st >>= 1) { if (i < st) red[i] += red[i + st]; __syncthreads(); }
    float mu = red[0] * (1.0f / DD); __syncthreads();
    float dx = o.x - mu, dy = o.y - mu, dz = o.z - mu, dw_ = o.w - mu;
    red[i] = dx * dx + dy * dy + dz * dz + dw_ * dw_; __syncthreads();
    for (int st = 128; st > 0; st >>= 1) { if (i < st) red[i] += red[i + st]; __syncthreads(); }
    float rstd = rsqrtf(red[0] * (1.0f / DD) + 1e-6f);
    float4 wv = reinterpret_cast<const float4*>(w)[i];
    float4 bv = reinterpret_cast<const float4*>(bb)[i];
    float4 xv = x4[i];
    xv.x += dx * rstd * wv.x + bv.x;
    xv.y += dy * rstd * wv.y + bv.y;
    xv.z += dz * rstd * wv.z + bv.z;
    xv.w += dw_ * rstd * wv.w + bv.w;
    x4[i] = xv;
    store_x3(xv, (long)row * DD + i * 4, nullptr, xh, xl, xf);
}

__global__ void final_ln_kernel(const float* __restrict__ X, const float* __restrict__ fw,
                                const float* __restrict__ fb, __half* __restrict__ Y)
{
    int row = blockIdx.x, i = threadIdx.x;
    const float4 x = reinterpret_cast<const float4*>(X + (long)row * DD)[i];
    __shared__ float red[256];
    red[i] = x.x + x.y + x.z + x.w; __syncthreads();
    for (int st = 128; st > 0; st >>= 1) { if (i < st) red[i] += red[i + st]; __syncthreads(); }
    float mu = red[0] * (1.0f / DD); __syncthreads();
    float dx = x.x - mu, dy = x.y - mu, dz = x.z - mu, dw_ = x.w - mu;
    red[i] = dx * dx + dy * dy + dz * dz + dw_ * dw_; __syncthreads();
    for (int st = 128; st > 0; st >>= 1) { if (i < st) red[i] += red[i + st]; __syncthreads(); }
    float rstd = rsqrtf(red[0] * (1.0f / DD) + 1e-5f);
    float4 wv = reinterpret_cast<const float4*>(fw)[i];
    float4 bv = reinterpret_cast<const float4*>(fb)[i];
    long off = (long)row * DD + i * 4;
    *reinterpret_cast<__half2*>(Y + off)     = __floats2half2_rn(dx * rstd * wv.x + bv.x, dy * rstd * wv.y + bv.y);
    *reinterpret_cast<__half2*>(Y + off + 2) = __floats2half2_rn(dz * rstd * wv.z + bv.z, dw_ * rstd * wv.w + bv.w);
}

// ---------------------------------------------------------------------------
extern "C" void kernel_launch(void* const* d_in, const int* in_sizes, int n_in,
                              void* d_out, int out_size)
{
    const int*   src = (const int*)d_in[0];
    const float* pe  = (const float*)d_in[1];
    const float* emb = (const float*)d_in[2];
    const float* qw  = (const float*)d_in[3];
    const float* qb  = (const float*)d_in[4];
    const float* kw  = (const float*)d_in[5];
    const float* kb  = (const float*)d_in[6];
    const float* vw  = (const float*)d_in[7];
    const float* vb  = (const float*)d_in[8];
    const float* lnw = (const float*)d_in[9];
    const float* lnb = (const float*)d_in[10];
    const float* fw  = (const float*)d_in[11];
    const float* fb  = (const float*)d_in[12];
    const float* dw  = (const float*)d_in[13];
    const float* db  = (const float*)d_in[14];
    float* out = (float*)d_out;

#define GA(sym, var) void* var##_; cudaGetSymbolAddress(&var##_, sym)
    GA(g_x, x);  GA(g_a, a);  GA(g_o, o);
    GA(g_xh, xh); GA(g_xl, xl); GA(g_xf, xf);
    GA(g_qh, qh); GA(g_ql, ql); GA(g_kh, kh); GA(g_kl, kl);
    GA(g_vf, vf); GA(g_wf, wf);
    GA(g_qwh, qwh); GA(g_qwl, qwl); GA(g_kwh, kwh); GA(g_kwl, kwl);
    GA(g_vwf, vwf); GA(g_dwf, dwf); GA(g_xnf, xnf);
#undef GA

    const int SMB = NSTAGE * 2 * (2 * 8192 + 2 * 8192);   // 196608 (split MT=128)
    const int SMS = NSTAGE * 2 * (2 * 4096 + 2 * 8192);   // 147456 (split MT=64)
    const int SMH = NSTAGE * 2 * (2 * 8192);              // 98304  (fp16)
    cudaFuncSetAttribute(qkv_kernel,   cudaFuncAttributeMaxDynamicSharedMemorySize, SMB);
    cudaFuncSetAttribute(sc_kernel,    cudaFuncAttributeMaxDynamicSharedMemorySize, SMS);
    cudaFuncSetAttribute(av_kernel,    cudaFuncAttributeMaxDynamicSharedMemorySize, SMH);
    cudaFuncSetAttribute(vocab_kernel, cudaFuncAttributeMaxDynamicSharedMemorySize, SMH);

    // per-launch weight conversions (deterministic, idempotent)
    {
        const int n4w = LL * DD * DD / 4;
        splitw_kernel<<<(n4w + 511) / 512, 512>>>((const float4*)qw, (bf16*)qwh_, (bf16*)qwl_, n4w);
        splitw_kernel<<<(n4w + 511) / 512, 512>>>((const float4*)kw, (bf16*)kwh_, (bf16*)kwl_, n4w);
        tohalf_kernel<<<(n4w + 511) / 512, 512>>>((const float4*)vw, (__half*)vwf_, n4w);
        const int n4d = VV * DD / 4;
        tohalf_kernel<<<(n4d + 511) / 512, 512>>>((const float4*)dw, (__half*)dwf_, n4d);
    }

    embed_pe_kernel<<<BB * TT, 256>>>(src, pe, emb, (float*)x_, (bf16*)xh_, (bf16*)xl_, (__half*)xf_);

    dim3 gqkv(DD / 128, (BB * TT) / 128, 3);
    dim3 gsc(TT / 128, TT / 64, BB);
    dim3 gav(TT / 128, TT / 128, BB);
    for (int l = 0; l < LL; l++) {
        const long wo = (long)l * DD * DD;
        QKVP p;
        p.xh = (const bf16*)xh_; p.xl = (const bf16*)xl_; p.xf = (const __half*)xf_;
        p.qwh = (const bf16*)qwh_ + wo; p.qwl = (const bf16*)qwl_ + wo;
        p.kwh = (const bf16*)kwh_ + wo; p.kwl = (const bf16*)kwl_ + wo;
        p.vwf = (const __half*)vwf_ + wo;
        p.qb = qb + l * DD; p.kb = kb + l * DD; p.vb = vb + l * DD;
        p.qh = (bf16*)qh_; p.ql = (bf16*)ql_;
        p.kh = (bf16*)kh_; p.kl = (bf16*)kl_;
        p.vf = (__half*)vf_;
        qkv_kernel<<<gqkv, 512, SMB>>>(p);
        sc_kernel<<<gsc, 256, SMS>>>((const bf16*)qh_, (const bf16*)ql_,
                                     (const bf16*)kh_, (const bf16*)kl_, (float*)a_);
        softmax_kernel<<<dim3(TT, BB), 256>>>((const float*)a_, (__half*)wf_);
        av_kernel<<<gav, 512, SMH>>>((const __half*)wf_, (const __half*)vf_, (float*)o_);
        ln_res_kernel<<<BB * TT, 256>>>((const float*)o_, lnw + l * DD, lnb + l * DD,
                                        (float*)x_, (bf16*)xh_, (bf16*)xl_, (__half*)xf_);
    }

    final_ln_kernel<<<BB * TT, 256>>>((const float*)x_, fw, fb, (__half*)xnf_);
    dim3 gf((BB * TT) / 128, VV / 128);   // x = M tiles (fast) -> dw tile shared in L2
    vocab_kernel<<<gf, 512, SMH>>>((const __half*)xnf_, (const __half*)dwf_, db, out);
}

// round 16
// speedup vs baseline: 1.1652x; 1.0828x over previous
#include <cuda_runtime.h>
#include <cuda_bf16.h>
#include <cuda_fp16.h>
#include <cstdint>

#define BB 2
#define TT 1024
#define DD 1024
#define VV 32000
#define LL 8
#define MD (TT * DD)
#define AA (TT * TT)

typedef __nv_bfloat16 bf16;

// fp32 masters
__device__ float g_x[BB * MD];
__device__ float g_a[BB * AA];
__device__ float g_o[BB * MD];
// split bf16 operands. xh/xl and weights are TILED (8KB blocks, pre-swizzled).
__device__ bf16 g_xh[BB * MD], g_xl[BB * MD];
__device__ bf16 g_qh[BB * MD], g_ql[BB * MD];      // row-major (sc operands)
__device__ bf16 g_kh[BB * MD], g_kl[BB * MD];      // row-major
__device__ bf16 g_qwh[LL * DD * DD], g_qwl[LL * DD * DD];   // tiled
__device__ bf16 g_kwh[LL * DD * DD], g_kwl[LL * DD * DD];   // tiled
// fp16 operands. xf, vwf, dwf, xnf TILED; vf, wf row-major.
__device__ __half g_xf[BB * MD];
__device__ __half g_vf[BB * MD];          // V^T [b][d][t] row-major
__device__ __half g_wf[BB * AA];
__device__ __half g_vwf[LL * DD * DD];    // tiled
__device__ __half g_dwf[VV * DD];         // tiled
__device__ __half g_xnf[BB * MD];         // tiled

#define NSTAGE 3
// 64B rows + XOR swizzle: chunk c (16B) of row r at r*64 + (c ^ ((r>>1)&3))*16.
#define SWZ(r, c) ((((uint32_t)(r)) << 6) + ((((c) ^ (((r) >> 1) & 3))) << 4))

// tiled element offset for 16-bit arrays, 128-row tiles, K elems/row.
// 8KB block per (tile, k32); within block: (r&127)*32 + swizzledchunk*8 + k&7.
__device__ __forceinline__ long toff(int rg, int k, int K) {
    return ((long)(rg >> 7) * (K >> 5) + (k >> 5)) * 4096
         + (long)(((rg & 127) << 5) + (((((k >> 3) & 3) ^ ((rg >> 1) & 3))) << 3) + (k & 7));
}

__device__ __forceinline__ uint32_t smem_u32(const void* p) {
    uint32_t a;
    asm("{ .reg .u64 t; cvta.to.shared.u64 t, %1; cvt.u32.u64 %0, t; }" : "=r"(a) : "l"(p));
    return a;
}
#define LDM4(r0, r1, r2, r3, ad) \
    asm volatile("ldmatrix.sync.aligned.m8n8.x4.shared.b16 {%0,%1,%2,%3},[%4];" \
                 : "=r"(r0), "=r"(r1), "=r"(r2), "=r"(r3) : "r"(ad))
#define MMA16B(c, a, b0_, b1_) \
    asm volatile("mma.sync.aligned.m16n8k16.row.col.f32.bf16.bf16.f32 " \
                 "{%0,%1,%2,%3},{%4,%5,%6,%7},{%8,%9},{%0,%1,%2,%3};" \
                 : "+f"((c)[0]), "+f"((c)[1]), "+f"((c)[2]), "+f"((c)[3]) \
                 : "r"((a)[0]), "r"((a)[1]), "r"((a)[2]), "r"((a)[3]), "r"(b0_), "r"(b1_))
#define MMA16H(c, a, b0_, b1_) \
    asm volatile("mma.sync.aligned.m16n8k16.row.col.f32.f16.f16.f32 " \
                 "{%0,%1,%2,%3},{%4,%5,%6,%7},{%8,%9},{%0,%1,%2,%3};" \
                 : "+f"((c)[0]), "+f"((c)[1]), "+f"((c)[2]), "+f"((c)[3]) \
                 : "r"((a)[0]), "r"((a)[1]), "r"((a)[2]), "r"((a)[3]), "r"(b0_), "r"(b1_))
#define CPA16(d, s) asm volatile("cp.async.cg.shared.global [%0], [%1], 16;" :: "r"(d), "l"(s))
#define CPCOMMIT()  asm volatile("cp.async.commit_group;" ::: "memory")
#define CPWAIT1()   asm volatile("cp.async.wait_group 1;" ::: "memory")

#define MBINIT(mb) asm volatile("mbarrier.init.shared.b64 [%0], 1;" :: "r"(mb) : "memory")
#define MBEXPECT(mb, bytes) \
    asm volatile("mbarrier.arrive.expect_tx.shared.b64 _, [%0], %1;" :: "r"(mb), "r"((uint32_t)(bytes)) : "memory")
#define BULK(dst, src, n, mb) \
    asm volatile("cp.async.bulk.shared::cluster.global.mbarrier::complete_tx::bytes [%0], [%1], %2, [%3];" \
                 :: "r"(dst), "l"(src), "r"((uint32_t)(n)), "r"(mb) : "memory")
__device__ __forceinline__ void mbwait(uint32_t mb, uint32_t par) {
    asm volatile(
        "{\n\t.reg .pred P;\n\tW%=:\n\t"
        "mbarrier.try_wait.parity.acquire.cta.shared::cta.b64 P, [%0], %1, 0x989680;\n\t"
        "@P bra.uni D%=;\n\tbra.uni W%=;\n\tD%=:\n\t}" :: "r"(mb), "r"(par) : "memory");
}

__device__ __forceinline__ void bsplit(float v, bf16& h, bf16& l) {
    h = __float2bfloat16_rn(v);
    l = __float2bfloat16_rn(v - __bfloat162float(h));
}

// ---------------------------------------------------------------------------
// Shared compute tile: split (hi/lo) 32-K block. 512 thr, 4x4 warps of 32x32.
// ---------------------------------------------------------------------------
struct LaneIdx {
    int a_ml, a_c0, b_nl, b_c0, wm, wn, lane;
};
__device__ __forceinline__ LaneIdx laneidx() {
    LaneIdx li;
    int tid = threadIdx.x;
    li.lane = tid & 31;
    int wrp = tid >> 5;
    li.wm = wrp >> 2; li.wn = wrp & 3;
    li.a_ml = (li.lane & 7) + ((li.lane >> 3) & 1) * 8;
    li.a_c0 = li.lane >> 4;
    li.b_nl = (li.lane & 7) + ((li.lane >> 4) << 3);
    li.b_c0 = (li.lane >> 3) & 1;
    return li;
}

__device__ __forceinline__ void compute32_split(const LaneIdx& li, uint32_t ahb, uint32_t alb,
                                                uint32_t bhb, uint32_t blb, float acc[2][4][4]) {
#pragma unroll
    for (int ks = 0; ks < 2; ks++) {
        uint32_t bhf[8], blf[8];
#pragma unroll
        for (int p = 0; p < 2; p++) {
            const uint32_t boff = SWZ(li.wn * 32 + p * 16 + li.b_nl, ks * 2 + li.b_c0);
            LDM4(bhf[p * 4 + 0], bhf[p * 4 + 1], bhf[p * 4 + 2], bhf[p * 4 + 3], bhb + boff);
            LDM4(blf[p * 4 + 0], blf[p * 4 + 1], blf[p * 4 + 2], blf[p * 4 + 3], blb + boff);
        }
#pragma unroll
        for (int mt = 0; mt < 2; mt++) {
            uint32_t ahf[4], alf[4];
            const uint32_t aoff = SWZ(li.wm * 32 + mt * 16 + li.a_ml, ks * 2 + li.a_c0);
            LDM4(ahf[0], ahf[1], ahf[2], ahf[3], ahb + aoff);
            LDM4(alf[0], alf[1], alf[2], alf[3], alb + aoff);
#pragma unroll
            for (int nt = 0; nt < 4; nt++) {
                const int bi = (nt >> 1) * 4 + (nt & 1) * 2;
                float* c = acc[mt][nt];
                MMA16B(c, ahf, bhf[bi], bhf[bi + 1]);
                MMA16B(c, ahf, blf[bi], blf[bi + 1]);
                MMA16B(c, alf, bhf[bi], bhf[bi + 1]);
            }
        }
    }
}
__device__ __forceinline__ void compute32_h(const LaneIdx& li, uint32_t ab, uint32_t bb2,
                                            float acc[2][4][4]) {
#pragma unroll
    for (int ks = 0; ks < 2; ks++) {
        uint32_t bhf[8];
#pragma unroll
        for (int p = 0; p < 2; p++) {
            const uint32_t boff = SWZ(li.wn * 32 + p * 16 + li.b_nl, ks * 2 + li.b_c0);
            LDM4(bhf[p * 4 + 0], bhf[p * 4 + 1], bhf[p * 4 + 2], bhf[p * 4 + 3], bb2 + boff);
        }
#pragma unroll
        for (int mt = 0; mt < 2; mt++) {
            uint32_t ahf[4];
            const uint32_t aoff = SWZ(li.wm * 32 + mt * 16 + li.a_ml, ks * 2 + li.a_c0);
            LDM4(ahf[0], ahf[1], ahf[2], ahf[3], ab + aoff);
#pragma unroll
            for (int nt = 0; nt < 4; nt++) {
                const int bi = (nt >> 1) * 4 + (nt & 1) * 2;
                MMA16H(acc[mt][nt], ahf, bhf[bi], bhf[bi + 1]);
            }
        }
    }
}

// ---------------------------------------------------------------------------
// BULK split core (Q/K proj): MT=128, 512 thr, all operands tiled-bulk.
// smem = 3 stages x 64KB + mbars. BIAS per-N. OUT bf16 hi/lo row-major.
// ---------------------------------------------------------------------------
__device__ __forceinline__ void gemm_bulk_split(
    const bf16* __restrict__ AhT, const bf16* __restrict__ AlT,
    const bf16* __restrict__ BhT, const bf16* __restrict__ BlT,
    const float* __restrict__ bias,
    bf16* __restrict__ Ch, bf16* __restrict__ Cl, int ldc,
    int m0, int n0, int K)
{
    constexpr int STG32 = 32768;   // Ah,Al,Bh,Bl x 8KB
    constexpr int STG64 = 65536;
    extern __shared__ uint16_t sm[];
    const uint32_t sb = smem_u32(sm);
    const uint32_t mb0 = sb + NSTAGE * STG64;
    const int tid = threadIdx.x;
    const LaneIdx li = laneidx();
    const int S2 = K >> 6;
    const int KB = K >> 5;   // 8KB blocks per tile-row

    const char* Ah = (const char*)(AhT) + ((long)(m0 >> 7) * KB) * 8192;
    const char* Al = (const char*)(AlT) + ((long)(m0 >> 7) * KB) * 8192;
    const char* Bh = (const char*)(BhT) + ((long)(n0 >> 7) * KB) * 8192;
    const char* Bl = (const char*)(BlT) + ((long)(n0 >> 7) * KB) * 8192;

    if (tid == 0) { MBINIT(mb0); MBINIT(mb0 + 8); MBINIT(mb0 + 16); }
    __syncthreads();

    auto issue = [&](int s2) {
        const uint32_t mb = mb0 + 8 * (s2 % NSTAGE);
        MBEXPECT(mb, STG64);
#pragma unroll
        for (int j = 0; j < 2; j++) {
            const int k32 = 2 * s2 + j;
            const uint32_t db = sb + (uint32_t)(s2 % NSTAGE) * STG64 + (uint32_t)j * STG32;
            BULK(db,         Ah + (long)k32 * 8192, 8192, mb);
            BULK(db + 8192,  Al + (long)k32 * 8192, 8192, mb);
            BULK(db + 16384, Bh + (long)k32 * 8192, 8192, mb);
            BULK(db + 24576, Bl + (long)k32 * 8192, 8192, mb);
        }
    };

    if (tid == 0) { issue(0); issue(1); }

    float acc[2][4][4] = {};
    for (int s2 = 0; s2 < S2; s2++) {
        mbwait(mb0 + 8 * (s2 % NSTAGE), (uint32_t)((s2 / NSTAGE) & 1));
        __syncthreads();
        if (tid == 0 && s2 + 2 < S2) issue(s2 + 2);
        const uint32_t stb = sb + (uint32_t)(s2 % NSTAGE) * STG64;
        compute32_split(li, stb, stb + 8192, stb + 16384, stb + 24576, acc);
        compute32_split(li, stb + STG32, stb + STG32 + 8192, stb + STG32 + 16384, stb + STG32 + 24576, acc);
    }

    const int er = li.lane >> 2, ec = (li.lane & 3) * 2;
#pragma unroll
    for (int mt = 0; mt < 2; mt++) {
        const int m = m0 + li.wm * 32 + mt * 16 + er;
#pragma unroll
        for (int nt = 0; nt < 4; nt++) {
            const int n = n0 + li.wn * 32 + nt * 8 + ec;
            const float bn0 = bias[n], bn1 = bias[n + 1];
            const float* c = acc[mt][nt];
            float v00 = c[0] + bn0, v01 = c[1] + bn1;
            float v10 = c[2] + bn0, v11 = c[3] + bn1;
            bf16 h0, l0, h1, l1;
            bsplit(v00, h0, l0); bsplit(v01, h1, l1);
            *reinterpret_cast<__nv_bfloat162*>(Ch + (long)m * ldc + n) = __halves2bfloat162(h0, h1);
            *reinterpret_cast<__nv_bfloat162*>(Cl + (long)m * ldc + n) = __halves2bfloat162(l0, l1);
            bsplit(v10, h0, l0); bsplit(v11, h1, l1);
            *reinterpret_cast<__nv_bfloat162*>(Ch + (long)(m + 8) * ldc + n) = __halves2bfloat162(h0, h1);
            *reinterpret_cast<__nv_bfloat162*>(Cl + (long)(m + 8) * ldc + n) = __halves2bfloat162(l0, l1);
        }
    }
}

// ---------------------------------------------------------------------------
// BULK fp16 core (V proj / vocab): MT=128, 512 thr, both operands tiled-bulk.
// BIAS: 1 per-N, 2 per-M. OUT: 0 fp32 Cf, 1 fp16 Chf.
// ---------------------------------------------------------------------------
template <int BIAS, int OUT>
__device__ __forceinline__ void gemm_bulk_h(
    const __half* __restrict__ AT, const __half* __restrict__ BT,
    const float* __restrict__ bias,
    float* __restrict__ Cf, __half* __restrict__ Chf, int ldc,
    int m0, int n0, int K)
{
    constexpr int STG32 = 16384;   // A,B x 8KB
    constexpr int STG64 = 32768;
    extern __shared__ uint16_t sm[];
    const uint32_t sb = smem_u32(sm);
    const uint32_t mb0 = sb + NSTAGE * STG64;
    const int tid = threadIdx.x;
    const LaneIdx li = laneidx();
    const int S2 = K >> 6;
    const int KB = K >> 5;

    const char* Ab = (const char*)(AT) + ((long)(m0 >> 7) * KB) * 8192;
    const char* Bb = (const char*)(BT) + ((long)(n0 >> 7) * KB) * 8192;

    if (tid == 0) { MBINIT(mb0); MBINIT(mb0 + 8); MBINIT(mb0 + 16); }
    __syncthreads();

    auto issue = [&](int s2) {
        const uint32_t mb = mb0 + 8 * (s2 % NSTAGE);
        MBEXPECT(mb, STG64);
#pragma unroll
        for (int j = 0; j < 2; j++) {
            const int k32 = 2 * s2 + j;
            const uint32_t db = sb + (uint32_t)(s2 % NSTAGE) * STG64 + (uint32_t)j * STG32;
            BULK(db,        Ab + (long)k32 * 8192, 8192, mb);
            BULK(db + 8192, Bb + (long)k32 * 8192, 8192, mb);
        }
    };

    if (tid == 0) { issue(0); issue(1); }

    float acc[2][4][4] = {};
    for (int s2 = 0; s2 < S2; s2++) {
        mbwait(mb0 + 8 * (s2 % NSTAGE), (uint32_t)((s2 / NSTAGE) & 1));
        __syncthreads();
        if (tid == 0 && s2 + 2 < S2) issue(s2 + 2);
        const uint32_t stb = sb + (uint32_t)(s2 % NSTAGE) * STG64;
        compute32_h(li, stb, stb + 8192, acc);
        compute32_h(li, stb + STG32, stb + STG32 + 8192, acc);
    }

    const int er = li.lane >> 2, ec = (li.lane & 3) * 2;
#pragma unroll
    for (int mt = 0; mt < 2; mt++) {
        const int m = m0 + li.wm * 32 + mt * 16 + er;
        float bm0 = 0.f, bm8 = 0.f;
        if (BIAS == 2) { bm0 = bias[m]; bm8 = bias[m + 8]; }
#pragma unroll
        for (int nt = 0; nt < 4; nt++) {
            const int n = n0 + li.wn * 32 + nt * 8 + ec;
            float bn0 = 0.f, bn1 = 0.f;
            if (BIAS == 1) { bn0 = bias[n]; bn1 = bias[n + 1]; }
            const float* c = acc[mt][nt];
            float v00 = c[0] + bn0 + bm0, v01 = c[1] + bn1 + bm0;
            float v10 = c[2] + bn0 + bm8, v11 = c[3] + bn1 + bm8;
            if (OUT == 0) {
                *reinterpret_cast<float2*>(Cf + (long)m * ldc + n) = make_float2(v00, v01);
                *reinterpret_cast<float2*>(Cf + (long)(m + 8) * ldc + n) = make_float2(v10, v11);
            } else {
                *reinterpret_cast<__half2*>(Chf + (long)m * ldc + n) = __floats2half2_rn(v00, v01);
                *reinterpret_cast<__half2*>(Chf + (long)(m + 8) * ldc + n) = __floats2half2_rn(v10, v11);
            }
        }
    }
}

// ---------------------------------------------------------------------------
// OLD split core (sc): MT=64, 256 thr, 3-stage cp.async. [R12 proven]
// ---------------------------------------------------------------------------
__device__ __forceinline__ void gemm_core_sc(
    const bf16* __restrict__ Ah, const bf16* __restrict__ Al, int lda,
    const bf16* __restrict__ Bh, const bf16* __restrict__ Bl, int ldb,
    float* __restrict__ Cf, int ldc, int m0, int n0, int Keff)
{
    constexpr int ABY = 64 * 64;
    constexpr int BBY = 8192;
    constexpr int STG32 = 2 * ABY + 2 * BBY;
    constexpr int STG64 = 2 * STG32;
    extern __shared__ uint16_t sm[];
    const uint32_t sb = smem_u32(sm);
    const int tid = threadIdx.x, lane = tid & 31, wrp = tid >> 5;
    const int wm = wrp >> 2, wn = wrp & 3;
    const int S2 = Keff >> 6;

    const int a_ml = (lane & 7) + ((lane >> 3) & 1) * 8;
    const int a_c0 = lane >> 4;
    const int b_nl = (lane & 7) + ((lane >> 4) << 3);
    const int b_c0 = (lane >> 3) & 1;

    const int row = tid >> 2, ch = tid & 3;
    const bf16* Aph = Ah + (long)(m0 + row) * lda + ch * 8;
    const bf16* Apl = Al + (long)(m0 + row) * lda + ch * 8;
    const bf16* Bph = Bh + (long)(n0 + row) * ldb + ch * 8;
    const bf16* Bpl = Bl + (long)(n0 + row) * ldb + ch * 8;
    const uint32_t swz = SWZ(row, ch);
    const uint32_t swz2 = SWZ(row + 64, ch);

    auto issue32 = [&](int k32, uint32_t db) {
        const int k0 = k32 << 5;
        CPA16(db + swz,                  Aph + k0);
        CPA16(db + ABY + swz,            Apl + k0);
        CPA16(db + 2 * ABY + swz,        Bph + k0);
        CPA16(db + 2 * ABY + swz2,       Bph + (long)64 * ldb + k0);
        CPA16(db + 2 * ABY + BBY + swz,  Bpl + k0);
        CPA16(db + 2 * ABY + BBY + swz2, Bpl + (long)64 * ldb + k0);
    };
    auto issue = [&](int s2) {
        const uint32_t db = sb + (uint32_t)(s2 % NSTAGE) * STG64;
        issue32(2 * s2, db);
        issue32(2 * s2 + 1, db + STG32);
        CPCOMMIT();
    };

    float acc[2][4][4] = {};
    auto compute32 = [&](uint32_t stb) {
        const uint32_t ahb = stb, alb = stb + ABY, bhb = stb + 2 * ABY, blb = bhb + BBY;
#pragma unroll
        for (int ks = 0; ks < 2; ks++) {
            uint32_t bhf[8], blf[8];
#pragma unroll
            for (int p = 0; p < 2; p++) {
                const uint32_t boff = SWZ(wn * 32 + p * 16 + b_nl, ks * 2 + b_c0);
                LDM4(bhf[p * 4 + 0], bhf[p * 4 + 1], bhf[p * 4 + 2], bhf[p * 4 + 3], bhb + boff);
                LDM4(blf[p * 4 + 0], blf[p * 4 + 1], blf[p * 4 + 2], blf[p * 4 + 3], blb + boff);
            }
#pragma unroll
            for (int mt = 0; mt < 2; mt++) {
                uint32_t ahf[4], alf[4];
                const uint32_t aoff = SWZ(wm * 32 + mt * 16 + a_ml, ks * 2 + a_c0);
                LDM4(ahf[0], ahf[1], ahf[2], ahf[3], ahb + aoff);
                LDM4(alf[0], alf[1], alf[2], alf[3], alb + aoff);
#pragma unroll
                for (int nt = 0; nt < 4; nt++) {
                    const int bi = (nt >> 1) * 4 + (nt & 1) * 2;
                    float* c = acc[mt][nt];
                    MMA16B(c, ahf, bhf[bi], bhf[bi + 1]);
                    MMA16B(c, ahf, blf[bi], blf[bi + 1]);
                    MMA16B(c, alf, bhf[bi], bhf[bi + 1]);
                }
            }
        }
    };

    issue(0); issue(1);
    for (int s2 = 0; s2 < S2; s2++) {
        CPWAIT1();
        __syncthreads();
        if (s2 + 2 < S2) issue(s2 + 2); else CPCOMMIT();
        const uint32_t stb = sb + (uint32_t)(s2 % NSTAGE) * STG64;
        compute32(stb);
        compute32(stb + STG32);
    }

    const int er = lane >> 2, ec = (lane & 3) * 2;
#pragma unroll
    for (int mt = 0; mt < 2; mt++) {
        const int m = m0 + wm * 32 + mt * 16 + er;
#pragma unroll
        for (int nt = 0; nt < 4; nt++) {
            const int n = n0 + wn * 32 + nt * 8 + ec;
            const float* c = acc[mt][nt];
            *reinterpret_cast<float2*>(Cf + (long)m * ldc + n) = make_float2(c[0], c[1]);
            *reinterpret_cast<float2*>(Cf + (long)(m + 8) * ldc + n) = make_float2(c[2], c[3]);
        }
    }
}

// ---------------------------------------------------------------------------
// OLD fp16 core (av): 512 thr, 3-stage cp.async, row-major operands. [R12]
// ---------------------------------------------------------------------------
__device__ __forceinline__ void gemm_core_av(
    const __half* __restrict__ A, int lda, const __half* __restrict__ B, int ldb,
    float* __restrict__ Cf, int ldc, int m0, int n0, int Keff)
{
    constexpr int BBY = 8192;
    constexpr int STG32 = 2 * BBY;
    constexpr int STG64 = 2 * STG32;
    extern __shared__ uint16_t sm[];
    const uint32_t sb = smem_u32(sm);
    const int tid = threadIdx.x;
    const LaneIdx li = laneidx();
    const int S2 = Keff >> 6;

    const int row = tid >> 2, ch = tid & 3;
    const __half* Ap = A + (long)(m0 + row) * lda + ch * 8;
    const __half* Bp = B + (long)(n0 + row) * ldb + ch * 8;
    const uint32_t swz = SWZ(row, ch);

    auto issue = [&](int s2) {
        const uint32_t db = sb + (uint32_t)(s2 % NSTAGE) * STG64;
#pragma unroll
        for (int j = 0; j < 2; j++) {
            const int k0 = (2 * s2 + j) << 5;
            CPA16(db + j * STG32 + swz,       Ap + k0);
            CPA16(db + j * STG32 + BBY + swz, Bp + k0);
        }
        CPCOMMIT();
    };

    float acc[2][4][4] = {};
    issue(0); issue(1);
    for (int s2 = 0; s2 < S2; s2++) {
        CPWAIT1();
        __syncthreads();
        if (s2 + 2 < S2) issue(s2 + 2); else CPCOMMIT();
        const uint32_t stb = sb + (uint32_t)(s2 % NSTAGE) * STG64;
        compute32_h(li, stb, stb + BBY, acc);
        compute32_h(li, stb + STG32, stb + STG32 + BBY, acc);
    }

    const int er = li.lane >> 2, ec = (li.lane & 3) * 2;
#pragma unroll
    for (int mt = 0; mt < 2; mt++) {
        const int m = m0 + li.wm * 32 + mt * 16 + er;
#pragma unroll
        for (int nt = 0; nt < 4; nt++) {
            const int n = n0 + li.wn * 32 + nt * 8 + ec;
            const float* c = acc[mt][nt];
            *reinterpret_cast<float2*>(Cf + (long)m * ldc + n) = make_float2(c[0], c[1]);
            *reinterpret_cast<float2*>(Cf + (long)(m + 8) * ldc + n) = make_float2(c[2], c[3]);
        }
    }
}

// ---------------------------------------------------------------------------
// Kernel wrappers
// ---------------------------------------------------------------------------
struct QKVP {
    const bf16 *xh, *xl;          // tiled
    const __half *xf;             // tiled
    const bf16 *qwh, *qwl, *kwh, *kwl;   // tiled
    const __half *vwf;            // tiled
    const float *qb, *kb, *vb;
    bf16 *qh, *ql, *kh, *kl;      // row-major out
    __half *vf;                   // row-major out
};

__global__ void __launch_bounds__(512) qkv_kernel(QKVP p)
{
    const int bx = blockIdx.x, by = blockIdx.y, bz = blockIdx.z;
    if (bz == 0) {
        gemm_bulk_split(p.xh, p.xl, p.qwh, p.qwl, p.qb, p.qh, p.ql, DD,
                        by * 128, bx * 128, DD);
    } else if (bz == 1) {
        gemm_bulk_split(p.xh, p.xl, p.kwh, p.kwl, p.kb, p.kh, p.kl, DD,
                        by * 128, bx * 128, DD);
    } else {
        const int b = by >> 3, dt = by & 7;
        gemm_bulk_h<2, 1>(p.vwf, p.xf + (long)b * MD, p.vb,
                          nullptr, p.vf + (long)b * MD, TT, dt * 128, bx * 128, DD);
    }
}

__global__ void __launch_bounds__(256) sc_kernel(const bf16* __restrict__ qh, const bf16* __restrict__ ql,
                                                 const bf16* __restrict__ kh, const bf16* __restrict__ kl,
                                                 float* __restrict__ a)
{
    const int bx = blockIdx.x, by = blockIdx.y, b = blockIdx.z;
    if (2 * bx > by) return;
    gemm_core_sc(qh + (long)b * MD, ql + (long)b * MD, DD,
                 kh + (long)b * MD, kl + (long)b * MD, DD,
                 a + (long)b * AA, TT, by * 64, bx * 128, DD);
}

__global__ void __launch_bounds__(512, 2) av_kernel(const __half* __restrict__ wf,
                                                    const __half* __restrict__ vf,
                                                    float* __restrict__ o)
{
    const int bx = blockIdx.x, by = blockIdx.y, b = blockIdx.z;
    gemm_core_av(wf + (long)b * AA, TT, vf + (long)b * MD, TT,
                 o + (long)b * MD, DD, by * 128, bx * 128, min(TT, by * 128 + 128));
}

__global__ void __launch_bounds__(512) vocab_kernel(const __half* __restrict__ xn,   // tiled
                                                    const __half* __restrict__ dwf,  // tiled
                                                    const float* __restrict__ db,
                                                    float* __restrict__ out)
{
    gemm_bulk_h<1, 0>(xn, dwf, db, out, nullptr, VV, blockIdx.x * 128, blockIdx.y * 128, DD);
}

// ---------------------------------------------------------------------------
// Converters (write TILED layouts) + elementwise
// ---------------------------------------------------------------------------
__global__ void splitw_tiled(const float* __restrict__ src, bf16* __restrict__ h,
                             bf16* __restrict__ l, int nchunks)
{
    int i = blockIdx.x * blockDim.x + threadIdx.x;
    if (i >= nchunks) return;
    const int rg = i >> 7, k = (i & 127) << 3;   // K = 1024 fixed
    const float4* s = reinterpret_cast<const float4*>(src + (long)rg * 1024 + k);
    float4 v0 = s[0], v1 = s[1];
    bf16 hh[8], ll[8];
    bsplit(v0.x, hh[0], ll[0]); bsplit(v0.y, hh[1], ll[1]);
    bsplit(v0.z, hh[2], ll[2]); bsplit(v0.w, hh[3], ll[3]);
    bsplit(v1.x, hh[4], ll[4]); bsplit(v1.y, hh[5], ll[5]);
    bsplit(v1.z, hh[6], ll[6]); bsplit(v1.w, hh[7], ll[7]);
    long off = toff(rg, k, 1024);
    *reinterpret_cast<uint4*>(h + off) = *reinterpret_cast<uint4*>(hh);
    *reinterpret_cast<uint4*>(l + off) = *reinterpret_cast<uint4*>(ll);
}

__global__ void tohalf_tiled(const float* __restrict__ src, __half* __restrict__ dst, int nchunks)
{
    int i = blockIdx.x * blockDim.x + threadIdx.x;
    if (i >= nchunks) return;
    const int rg = i >> 7, k = (i & 127) << 3;
    const float4* s = reinterpret_cast<const float4*>(src + (long)rg * 1024 + k);
    float4 v0 = s[0], v1 = s[1];
    __half hh[8];
    *reinterpret_cast<__half2*>(hh)     = __floats2half2_rn(v0.x, v0.y);
    *reinterpret_cast<__half2*>(hh + 2) = __floats2half2_rn(v0.z, v0.w);
    *reinterpret_cast<__half2*>(hh + 4) = __floats2half2_rn(v1.x, v1.y);
    *reinterpret_cast<__half2*>(hh + 6) = __floats2half2_rn(v1.z, v1.w);
    *reinterpret_cast<uint4*>(dst + toff(rg, k, 1024)) = *reinterpret_cast<uint4*>(hh);
}

// store x in fp32 row-major + TILED xh/xl/xf
__device__ __forceinline__ void store_x3(float4 v, int rg, int k, float* X,
                                         bf16* xh, bf16* xl, __half* xf)
{
    if (X) *reinterpret_cast<float4*>(X + (long)rg * DD + k) = v;
    bf16 h0, l0, h1, l1, h2, l2, h3, l3;
    bsplit(v.x, h0, l0); bsplit(v.y, h1, l1); bsplit(v.z, h2, l2); bsplit(v.w, h3, l3);
    long off = toff(rg, k, DD);
    *reinterpret_cast<__nv_bfloat162*>(xh + off)     = __halves2bfloat162(h0, h1);
    *reinterpret_cast<__nv_bfloat162*>(xh + off + 2) = __halves2bfloat162(h2, h3);
    *reinterpret_cast<__nv_bfloat162*>(xl + off)     = __halves2bfloat162(l0, l1);
    *reinterpret_cast<__nv_bfloat162*>(xl + off + 2) = __halves2bfloat162(l2, l3);
    *reinterpret_cast<__half2*>(xf + off)     = __floats2half2_rn(v.x, v.y);
    *reinterpret_cast<__half2*>(xf + off + 2) = __floats2half2_rn(v.z, v.w);
}

__global__ void embed_pe_kernel(const int* __restrict__ src, const float* __restrict__ pe,
                                const float* __restrict__ embed, float* __restrict__ x,
                                bf16* __restrict__ xh, bf16* __restrict__ xl, __half* __restrict__ xf)
{
    int row = blockIdx.x, b = row >> 10;
    long tok = src[row];
    const float4* e = reinterpret_cast<const float4*>(embed + tok * (long)DD);
    const float4* p = reinterpret_cast<const float4*>(pe + (long)b * DD);
    int i = threadIdx.x;
    float4 ev = e[i], pv = p[i];
    float4 v = make_float4(ev.x + pv.x, ev.y + pv.y, ev.z + pv.z, ev.w + pv.w);
    store_x3(v, row, i * 4, x, xh, xl, xf);
}

__global__ void softmax_kernel(const float* __restrict__ A, __half* __restrict__ Wf)
{
    int t = blockIdx.x, b = blockIdx.y;
    const float* row = A + ((long)b * TT + t) * TT;
    __half* wf = Wf + ((long)b * TT + t) * TT;
    int n = t + 1, i = threadIdx.x;
    __shared__ float red[256];
    __shared__ float rowe[TT];
    float m = -1e30f;
    for (int s = i; s < n; s += 256) m = fmaxf(m, row[s]);
    red[i] = m; __syncthreads();
    for (int st = 128; st > 0; st >>= 1) { if (i < st) red[i] = fmaxf(red[i], red[i + st]); __syncthreads(); }
    m = red[0]; __syncthreads();
    float sum = 0.f;
    for (int s = i; s < n; s += 256) { float e = expf(row[s] - m); rowe[s] = e; sum += e; }
    red[i] = sum; __syncthreads();
    for (int st = 128; st > 0; st >>= 1) { if (i < st) red[i] += red[i + st]; __syncthreads(); }
    float inv = 1.0f / red[0];
    for (int s = i; s < TT; s += 256)
        wf[s] = (s < n) ? __float2half_rn(rowe[s] * inv) : __float2half_rn(0.f);
}

__global__ void ln_res_kernel(const float* __restrict__ O, const float* __restrict__ w,
                              const float* __restrict__ bb, float* __restrict__ X,
                              bf16* __restrict__ xh, bf16* __restrict__ xl, __half* __restrict__ xf)
{
    int row = blockIdx.x, i = threadIdx.x;
    const float4 o = reinterpret_cast<const float4*>(O + (long)row * DD)[i];
    float4* x4 = reinterpret_cast<float4*>(X + (long)row * DD);
    __shared__ float red[256];
    red[i] = o.x + o.y + o.z + o.w; __syncthreads();
    for (int st = 128; st > 0; st >>= 1) { if (i < st) red[i] += red[i + st]; __syncthreads(); }
    float mu = red[0] * (1.0f / DD); __syncthreads();
    float dx = o.x - mu, dy = o.y - mu, dz = o.z - mu, dw_ = o.w - mu;
    red[i] = dx * dx + dy * dy + dz * dz + dw_ * dw_; __syncthreads();
    for (int st = 128; st > 0; st >>= 1) { if (i < st) red[i] += red[i + st]; __syncthreads(); }
    float rstd = rsqrtf(red[0] * (1.0f / DD) + 1e-6f);
    float4 wv = reinterpret_cast<const float4*>(w)[i];
    float4 bv = reinterpret_cast<const float4*>(bb)[i];
    float4 xv = x4[i];
    xv.x += dx * rstd * wv.x + bv.x;
    xv.y += dy * rstd * wv.y + bv.y;
    xv.z += dz * rstd * wv.z + bv.z;
    xv.w += dw_ * rstd * wv.w + bv.w;
    x4[i] = xv;
    store_x3(xv, row, i * 4, nullptr, xh, xl, xf);
}

__global__ void final_ln_kernel(const float* __restrict__ X, const float* __restrict__ fw,
                                const float* __restrict__ fb, __half* __restrict__ Y)  // Y tiled
{
    int row = blockIdx.x, i = threadIdx.x;
    const float4 x = reinterpret_cast<const float4*>(X + (long)row * DD)[i];
    __shared__ float red[256];
    red[i] = x.x + x.y + x.z + x.w; __syncthreads();
    for (int st = 128; st > 0; st >>= 1) { if (i < st) red[i] += red[i + st]; __syncthreads(); }
    float mu = red[0] * (1.0f / DD); __syncthreads();
    float dx = x.x - mu, dy = x.y - mu, dz = x.z - mu, dw_ = x.w - mu;
    red[i] = dx * dx + dy * dy + dz * dz + dw_ * dw_; __syncthreads();
    for (int st = 128; st > 0; st >>= 1) { if (i < st) red[i] += red[i + st]; __syncthreads(); }
    float rstd = rsqrtf(red[0] * (1.0f / DD) + 1e-5f);
    float4 wv = reinterpret_cast<const float4*>(fw)[i];
    float4 bv = reinterpret_cast<const float4*>(fb)[i];
    long off = toff(row, i * 4, DD);
    *reinterpret_cast<__half2*>(Y + off)     = __floats2half2_rn(dx * rstd * wv.x + bv.x, dy * rstd * wv.y + bv.y);
    *reinterpret_cast<__half2*>(Y + off + 2) = __floats2half2_rn(dz * rstd * wv.z + bv.z, dw_ * rstd * wv.w + bv.w);
}

// ---------------------------------------------------------------------------
extern "C" void kernel_launch(void* const* d_in, const int* in_sizes, int n_in,
                              void* d_out, int out_size)
{
    const int*   src = (const int*)d_in[0];
    const float* pe  = (const float*)d_in[1];
    const float* emb = (const float*)d_in[2];
    const float* qw  = (const float*)d_in[3];
    const float* qb  = (const float*)d_in[4];
    const float* kw  = (const float*)d_in[5];
    const float* kb  = (const float*)d_in[6];
    const float* vw  = (const float*)d_in[7];
    const float* vb  = (const float*)d_in[8];
    const float* lnw = (const float*)d_in[9];
    const float* lnb = (const float*)d_in[10];
    const float* fw  = (const float*)d_in[11];
    const float* fb  = (const float*)d_in[12];
    const float* dw  = (const float*)d_in[13];
    const float* db  = (const float*)d_in[14];
    float* out = (float*)d_out;

#define GA(sym, var) void* var##_; cudaGetSymbolAddress(&var##_, sym)
    GA(g_x, x);  GA(g_a, a);  GA(g_o, o);
    GA(g_xh, xh); GA(g_xl, xl); GA(g_xf, xf);
    GA(g_qh, qh); GA(g_ql, ql); GA(g_kh, kh); GA(g_kl, kl);
    GA(g_vf, vf); GA(g_wf, wf);
    GA(g_qwh, qwh); GA(g_qwl, qwl); GA(g_kwh, kwh); GA(g_kwl, kwl);
    GA(g_vwf, vwf); GA(g_dwf, dwf); GA(g_xnf, xnf);
#undef GA

    const int SMB = NSTAGE * 65536 + 64;              // 196672 (bulk split)
    const int SMS = NSTAGE * 2 * (2 * 4096 + 2 * 8192);  // 147456 (sc)
    const int SMH = NSTAGE * 32768 + 64;              // 98368 (bulk fp16)
    const int SMA = NSTAGE * 2 * (2 * 8192);          // 98304 (av)
    cudaFuncSetAttribute(qkv_kernel,   cudaFuncAttributeMaxDynamicSharedMemorySize, SMB);
    cudaFuncSetAttribute(sc_kernel,    cudaFuncAttributeMaxDynamicSharedMemorySize, SMS);
    cudaFuncSetAttribute(av_kernel,    cudaFuncAttributeMaxDynamicSharedMemorySize, SMA);
    cudaFuncSetAttribute(vocab_kernel, cudaFuncAttributeMaxDynamicSharedMemorySize, SMH);

    // per-launch weight conversions -> TILED layouts (deterministic, idempotent)
    {
        const int ncw = LL * DD * DD / 8;
        splitw_tiled<<<(ncw + 511) / 512, 512>>>(qw, (bf16*)qwh_, (bf16*)qwl_, ncw);
        splitw_tiled<<<(ncw + 511) / 512, 512>>>(kw, (bf16*)kwh_, (bf16*)kwl_, ncw);
        tohalf_tiled<<<(ncw + 511) / 512, 512>>>(vw, (__half*)vwf_, ncw);
        const int ncd = VV * DD / 8;
        tohalf_tiled<<<(ncd + 511) / 512, 512>>>(dw, (__half*)dwf_, ncd);
    }

    embed_pe_kernel<<<BB * TT, 256>>>(src, pe, emb, (float*)x_, (bf16*)xh_, (bf16*)xl_, (__half*)xf_);

    dim3 gqkv(DD / 128, (BB * TT) / 128, 3);
    dim3 gsc(TT / 128, TT / 64, BB);
    dim3 gav(TT / 128, TT / 128, BB);
    for (int l = 0; l < LL; l++) {
        const long wo = (long)l * DD * DD;
        QKVP p;
        p.xh = (const bf16*)xh_; p.xl = (const bf16*)xl_; p.xf = (const __half*)xf_;
        p.qwh = (const bf16*)qwh_ + wo; p.qwl = (const bf16*)qwl_ + wo;
        p.kwh = (const bf16*)kwh_ + wo; p.kwl = (const bf16*)kwl_ + wo;
        p.vwf = (const __half*)vwf_ + wo;
        p.qb = qb + l * DD; p.kb = kb + l * DD; p.vb = vb + l * DD;
        p.qh = (bf16*)qh_; p.ql = (bf16*)ql_;
        p.kh = (bf16*)kh_; p.kl = (bf16*)kl_;
        p.vf = (__half*)vf_;
        qkv_kernel<<<gqkv, 512, SMB>>>(p);
        sc_kernel<<<gsc, 256, SMS>>>((const bf16*)qh_, (const bf16*)ql_,
                                     (const bf16*)kh_, (const bf16*)kl_, (float*)a_);
        softmax_kernel<<<dim3(TT, BB), 256>>>((const float*)a_, (__half*)wf_);
        av_kernel<<<gav, 512, SMA>>>((const __half*)wf_, (const __half*)vf_, (float*)o_);
        ln_res_kernel<<<BB * TT, 256>>>((const float*)o_, lnw + l * DD, lnb + l * DD,
                                        (float*)x_, (bf16*)xh_, (bf16*)xl_, (__half*)xf_);
    }

    final_ln_kernel<<<BB * TT, 256>>>((const float*)x_, fw, fb, (__half*)xnf_);
    dim3 gf((BB * TT) / 128, VV / 128);   // x = M tiles (fast) -> dwf tile shared in L2
    vocab_kernel<<<gf, 512, SMH>>>((const __half*)xnf_, (const __half*)dwf_, db, out);
}

// round 17
// speedup vs baseline: 1.2179x; 1.0452x over previous
#include <cuda_runtime.h>
#include <cuda_bf16.h>
#include <cuda_fp16.h>
#include <cstdint>

#define BB 2
#define TT 1024
#define DD 1024
#define VV 32000
#define LL 8
#define MD (TT * DD)
#define AA (TT * TT)

typedef __nv_bfloat16 bf16;

// fp32 masters
__device__ float g_x[BB * MD];
__device__ float g_a[BB * AA];
__device__ float g_o[BB * MD];
// TILED operands (8KB blocks of 128 rows x 32 k-elems, pre-swizzled)
__device__ bf16 g_xh[BB * MD], g_xl[BB * MD];
__device__ bf16 g_qh[BB * MD], g_ql[BB * MD];
__device__ bf16 g_kh[BB * MD], g_kl[BB * MD];
__device__ bf16 g_qwh[LL * DD * DD], g_qwl[LL * DD * DD];
__device__ bf16 g_kwh[LL * DD * DD], g_kwl[LL * DD * DD];
__device__ __half g_xf[BB * MD];
__device__ __half g_vf[BB * MD];          // V^T [b][d][t] tiled
__device__ __half g_wf[BB * AA];          // tiled
__device__ __half g_vwf[LL * DD * DD];
__device__ __half g_dwf[VV * DD];
__device__ __half g_xnf[BB * MD];

#define NSTAGE 3
// 64B rows + XOR swizzle: chunk c (16B) of row r at r*64 + (c ^ ((r>>1)&3))*16.
#define SWZ(r, c) ((((uint32_t)(r)) << 6) + ((((c) ^ (((r) >> 1) & 3))) << 4))

// tiled element offset for 16-bit arrays, 128-row tiles, K elems/row.
__device__ __forceinline__ long toff(int rg, int k, int K) {
    return ((long)(rg >> 7) * (K >> 5) + (k >> 5)) * 4096
         + (long)(((rg & 127) << 5) + (((((k >> 3) & 3) ^ ((rg >> 1) & 3))) << 3) + (k & 7));
}

__device__ __forceinline__ uint32_t smem_u32(const void* p) {
    uint32_t a;
    asm("{ .reg .u64 t; cvta.to.shared.u64 t, %1; cvt.u32.u64 %0, t; }" : "=r"(a) : "l"(p));
    return a;
}
#define LDM4(r0, r1, r2, r3, ad) \
    asm volatile("ldmatrix.sync.aligned.m8n8.x4.shared.b16 {%0,%1,%2,%3},[%4];" \
                 : "=r"(r0), "=r"(r1), "=r"(r2), "=r"(r3) : "r"(ad))
#define MMA16B(c, a, b0_, b1_) \
    asm volatile("mma.sync.aligned.m16n8k16.row.col.f32.bf16.bf16.f32 " \
                 "{%0,%1,%2,%3},{%4,%5,%6,%7},{%8,%9},{%0,%1,%2,%3};" \
                 : "+f"((c)[0]), "+f"((c)[1]), "+f"((c)[2]), "+f"((c)[3]) \
                 : "r"((a)[0]), "r"((a)[1]), "r"((a)[2]), "r"((a)[3]), "r"(b0_), "r"(b1_))
#define MMA16H(c, a, b0_, b1_) \
    asm volatile("mma.sync.aligned.m16n8k16.row.col.f32.f16.f16.f32 " \
                 "{%0,%1,%2,%3},{%4,%5,%6,%7},{%8,%9},{%0,%1,%2,%3};" \
                 : "+f"((c)[0]), "+f"((c)[1]), "+f"((c)[2]), "+f"((c)[3]) \
                 : "r"((a)[0]), "r"((a)[1]), "r"((a)[2]), "r"((a)[3]), "r"(b0_), "r"(b1_))

#define MBINIT(mb) asm volatile("mbarrier.init.shared.b64 [%0], 1;" :: "r"(mb) : "memory")
#define MBEXPECT(mb, bytes) \
    asm volatile("mbarrier.arrive.expect_tx.shared.b64 _, [%0], %1;" :: "r"(mb), "r"((uint32_t)(bytes)) : "memory")
#define BULK(dst, src, n, mb) \
    asm volatile("cp.async.bulk.shared::cluster.global.mbarrier::complete_tx::bytes [%0], [%1], %2, [%3];" \
                 :: "r"(dst), "l"(src), "r"((uint32_t)(n)), "r"(mb) : "memory")
__device__ __forceinline__ void mbwait(uint32_t mb, uint32_t par) {
    asm volatile(
        "{\n\t.reg .pred P;\n\tW%=:\n\t"
        "mbarrier.try_wait.parity.acquire.cta.shared::cta.b64 P, [%0], %1, 0x989680;\n\t"
        "@P bra.uni D%=;\n\tbra.uni W%=;\n\tD%=:\n\t}" :: "r"(mb), "r"(par) : "memory");
}

__device__ __forceinline__ void bsplit(float v, bf16& h, bf16& l) {
    h = __float2bfloat16_rn(v);
    l = __float2bfloat16_rn(v - __bfloat162float(h));
}

// ---------------------------------------------------------------------------
struct LaneIdx { int a_ml, a_c0, b_nl, b_c0, wm, wn, lane; };
__device__ __forceinline__ LaneIdx laneidx() {
    LaneIdx li;
    int tid = threadIdx.x;
    li.lane = tid & 31;
    int wrp = tid >> 5;
    li.wm = wrp >> 2; li.wn = wrp & 3;
    li.a_ml = (li.lane & 7) + ((li.lane >> 3) & 1) * 8;
    li.a_c0 = li.lane >> 4;
    li.b_nl = (li.lane & 7) + ((li.lane >> 4) << 3);
    li.b_c0 = (li.lane >> 3) & 1;
    return li;
}

__device__ __forceinline__ void compute32_split(const LaneIdx& li, uint32_t ahb, uint32_t alb,
                                                uint32_t bhb, uint32_t blb, float acc[2][4][4]) {
#pragma unroll
    for (int ks = 0; ks < 2; ks++) {
        uint32_t bhf[8], blf[8];
#pragma unroll
        for (int p = 0; p < 2; p++) {
            const uint32_t boff = SWZ(li.wn * 32 + p * 16 + li.b_nl, ks * 2 + li.b_c0);
            LDM4(bhf[p * 4 + 0], bhf[p * 4 + 1], bhf[p * 4 + 2], bhf[p * 4 + 3], bhb + boff);
            LDM4(blf[p * 4 + 0], blf[p * 4 + 1], blf[p * 4 + 2], blf[p * 4 + 3], blb + boff);
        }
#pragma unroll
        for (int mt = 0; mt < 2; mt++) {
            uint32_t ahf[4], alf[4];
            const uint32_t aoff = SWZ(li.wm * 32 + mt * 16 + li.a_ml, ks * 2 + li.a_c0);
            LDM4(ahf[0], ahf[1], ahf[2], ahf[3], ahb + aoff);
            LDM4(alf[0], alf[1], alf[2], alf[3], alb + aoff);
#pragma unroll
            for (int nt = 0; nt < 4; nt++) {
                const int bi = (nt >> 1) * 4 + (nt & 1) * 2;
                float* c = acc[mt][nt];
                MMA16B(c, ahf, bhf[bi], bhf[bi + 1]);
                MMA16B(c, ahf, blf[bi], blf[bi + 1]);
                MMA16B(c, alf, bhf[bi], bhf[bi + 1]);
            }
        }
    }
}
__device__ __forceinline__ void compute32_h(const LaneIdx& li, uint32_t ab, uint32_t bb2,
                                            float acc[2][4][4]) {
#pragma unroll
    for (int ks = 0; ks < 2; ks++) {
        uint32_t bhf[8];
#pragma unroll
        for (int p = 0; p < 2; p++) {
            const uint32_t boff = SWZ(li.wn * 32 + p * 16 + li.b_nl, ks * 2 + li.b_c0);
            LDM4(bhf[p * 4 + 0], bhf[p * 4 + 1], bhf[p * 4 + 2], bhf[p * 4 + 3], bb2 + boff);
        }
#pragma unroll
        for (int mt = 0; mt < 2; mt++) {
            uint32_t ahf[4];
            const uint32_t aoff = SWZ(li.wm * 32 + mt * 16 + li.a_ml, ks * 2 + li.a_c0);
            LDM4(ahf[0], ahf[1], ahf[2], ahf[3], ab + aoff);
#pragma unroll
            for (int nt = 0; nt < 4; nt++) {
                const int bi = (nt >> 1) * 4 + (nt & 1) * 2;
                MMA16H(acc[mt][nt], ahf, bhf[bi], bhf[bi + 1]);
            }
        }
    }
}

// ---------------------------------------------------------------------------
// BULK split core (Q/K proj): MT=128, 512 thr, all operands tiled-bulk.
// OUT: Ch/Cl TILED (K=ldK).
// ---------------------------------------------------------------------------
__device__ __forceinline__ void gemm_bulk_split(
    const bf16* __restrict__ AhT, const bf16* __restrict__ AlT,
    const bf16* __restrict__ BhT, const bf16* __restrict__ BlT,
    const float* __restrict__ bias,
    bf16* __restrict__ Ch, bf16* __restrict__ Cl, int ldK,
    int m0, int n0, int K)
{
    constexpr int STG32 = 32768;
    constexpr int STG64 = 65536;
    extern __shared__ uint16_t sm[];
    const uint32_t sb = smem_u32(sm);
    const uint32_t mb0 = sb + NSTAGE * STG64;
    const int tid = threadIdx.x;
    const LaneIdx li = laneidx();
    const int S2 = K >> 6;
    const int KB = K >> 5;

    const char* Ah = (const char*)(AhT) + ((long)(m0 >> 7) * KB) * 8192;
    const char* Al = (const char*)(AlT) + ((long)(m0 >> 7) * KB) * 8192;
    const char* Bh = (const char*)(BhT) + ((long)(n0 >> 7) * KB) * 8192;
    const char* Bl = (const char*)(BlT) + ((long)(n0 >> 7) * KB) * 8192;

    if (tid == 0) { MBINIT(mb0); MBINIT(mb0 + 8); MBINIT(mb0 + 16); }
    __syncthreads();

    auto issue = [&](int s2) {
        const uint32_t mb = mb0 + 8 * (s2 % NSTAGE);
        MBEXPECT(mb, STG64);
#pragma unroll
        for (int j = 0; j < 2; j++) {
            const int k32 = 2 * s2 + j;
            const uint32_t db = sb + (uint32_t)(s2 % NSTAGE) * STG64 + (uint32_t)j * STG32;
            BULK(db,         Ah + (long)k32 * 8192, 8192, mb);
            BULK(db + 8192,  Al + (long)k32 * 8192, 8192, mb);
            BULK(db + 16384, Bh + (long)k32 * 8192, 8192, mb);
            BULK(db + 24576, Bl + (long)k32 * 8192, 8192, mb);
        }
    };

    if (tid == 0) { issue(0); issue(1); }

    float acc[2][4][4] = {};
    for (int s2 = 0; s2 < S2; s2++) {
        mbwait(mb0 + 8 * (s2 % NSTAGE), (uint32_t)((s2 / NSTAGE) & 1));
        __syncthreads();
        if (tid == 0 && s2 + 2 < S2) issue(s2 + 2);
        const uint32_t stb = sb + (uint32_t)(s2 % NSTAGE) * STG64;
        compute32_split(li, stb, stb + 8192, stb + 16384, stb + 24576, acc);
        compute32_split(li, stb + STG32, stb + STG32 + 8192, stb + STG32 + 16384, stb + STG32 + 24576, acc);
    }

    const int er = li.lane >> 2, ec = (li.lane & 3) * 2;
#pragma unroll
    for (int mt = 0; mt < 2; mt++) {
        const int m = m0 + li.wm * 32 + mt * 16 + er;
#pragma unroll
        for (int nt = 0; nt < 4; nt++) {
            const int n = n0 + li.wn * 32 + nt * 8 + ec;
            const float bn0 = bias[n], bn1 = bias[n + 1];
            const float* c = acc[mt][nt];
            float v00 = c[0] + bn0, v01 = c[1] + bn1;
            float v10 = c[2] + bn0, v11 = c[3] + bn1;
            bf16 h0, l0, h1, l1;
            bsplit(v00, h0, l0); bsplit(v01, h1, l1);
            long of0 = toff(m, n, ldK);
            *reinterpret_cast<__nv_bfloat162*>(Ch + of0) = __halves2bfloat162(h0, h1);
            *reinterpret_cast<__nv_bfloat162*>(Cl + of0) = __halves2bfloat162(l0, l1);
            bsplit(v10, h0, l0); bsplit(v11, h1, l1);
            long of1 = toff(m + 8, n, ldK);
            *reinterpret_cast<__nv_bfloat162*>(Ch + of1) = __halves2bfloat162(h0, h1);
            *reinterpret_cast<__nv_bfloat162*>(Cl + of1) = __halves2bfloat162(l0, l1);
        }
    }
}

// ---------------------------------------------------------------------------
// BULK fp16 core: MT=128, 512 thr, both operands tiled-bulk.
// Kfull = stride, Keff = loop bound. BIAS: 0/1 per-N/2 per-M.
// OUT: 0 fp32 row-major Cf(ldc), 1 fp16 TILED Chf(K=ldc).
// ---------------------------------------------------------------------------
template <int BIAS, int OUT>
__device__ __forceinline__ void gemm_bulk_h(
    const __half* __restrict__ AT, const __half* __restrict__ BT,
    const float* __restrict__ bias,
    float* __restrict__ Cf, __half* __restrict__ Chf, int ldc,
    int m0, int n0, int Kfull, int Keff)
{
    constexpr int STG32 = 16384;
    constexpr int STG64 = 32768;
    extern __shared__ uint16_t sm[];
    const uint32_t sb = smem_u32(sm);
    const uint32_t mb0 = sb + NSTAGE * STG64;
    const int tid = threadIdx.x;
    const LaneIdx li = laneidx();
    const int S2 = Keff >> 6;
    const int KB = Kfull >> 5;

    const char* Ab = (const char*)(AT) + ((long)(m0 >> 7) * KB) * 8192;
    const char* Bb = (const char*)(BT) + ((long)(n0 >> 7) * KB) * 8192;

    if (tid == 0) { MBINIT(mb0); MBINIT(mb0 + 8); MBINIT(mb0 + 16); }
    __syncthreads();

    auto issue = [&](int s2) {
        const uint32_t mb = mb0 + 8 * (s2 % NSTAGE);
        MBEXPECT(mb, STG64);
#pragma unroll
        for (int j = 0; j < 2; j++) {
            const int k32 = 2 * s2 + j;
            const uint32_t db = sb + (uint32_t)(s2 % NSTAGE) * STG64 + (uint32_t)j * STG32;
            BULK(db,        Ab + (long)k32 * 8192, 8192, mb);
            BULK(db + 8192, Bb + (long)k32 * 8192, 8192, mb);
        }
    };

    if (tid == 0) { issue(0); issue(1); }

    float acc[2][4][4] = {};
    for (int s2 = 0; s2 < S2; s2++) {
        mbwait(mb0 + 8 * (s2 % NSTAGE), (uint32_t)((s2 / NSTAGE) & 1));
        __syncthreads();
        if (tid == 0 && s2 + 2 < S2) issue(s2 + 2);
        const uint32_t stb = sb + (uint32_t)(s2 % NSTAGE) * STG64;
        compute32_h(li, stb, stb + 8192, acc);
        compute32_h(li, stb + STG32, stb + STG32 + 8192, acc);
    }

    const int er = li.lane >> 2, ec = (li.lane & 3) * 2;
#pragma unroll
    for (int mt = 0; mt < 2; mt++) {
        const int m = m0 + li.wm * 32 + mt * 16 + er;
        float bm0 = 0.f, bm8 = 0.f;
        if (BIAS == 2) { bm0 = bias[m]; bm8 = bias[m + 8]; }
#pragma unroll
        for (int nt = 0; nt < 4; nt++) {
            const int n = n0 + li.wn * 32 + nt * 8 + ec;
            float bn0 = 0.f, bn1 = 0.f;
            if (BIAS == 1) { bn0 = bias[n]; bn1 = bias[n + 1]; }
            const float* c = acc[mt][nt];
            float v00 = c[0] + bn0 + bm0, v01 = c[1] + bn1 + bm0;
            float v10 = c[2] + bn0 + bm8, v11 = c[3] + bn1 + bm8;
            if (OUT == 0) {
                *reinterpret_cast<float2*>(Cf + (long)m * ldc + n) = make_float2(v00, v01);
                *reinterpret_cast<float2*>(Cf + (long)(m + 8) * ldc + n) = make_float2(v10, v11);
            } else {
                *reinterpret_cast<__half2*>(Chf + toff(m, n, ldc)) = __floats2half2_rn(v00, v01);
                *reinterpret_cast<__half2*>(Chf + toff(m + 8, n, ldc)) = __floats2half2_rn(v10, v11);
            }
        }
    }
}

// ---------------------------------------------------------------------------
// BULK split core for scores: MT=64, 256 thr. A slice = contiguous 4KB
// half-block; B = full 8KB blocks. OUT fp32 row-major.
// ---------------------------------------------------------------------------
__device__ __forceinline__ void gemm_bulk_sc(
    const bf16* __restrict__ AhT, const bf16* __restrict__ AlT,
    const bf16* __restrict__ BhT, const bf16* __restrict__ BlT,
    float* __restrict__ Cf, int ldc, int m0, int n0, int K)
{
    constexpr int STG32 = 24576;   // Ah 4K, Al 4K, Bh 8K, Bl 8K
    constexpr int STG64 = 49152;
    extern __shared__ uint16_t sm[];
    const uint32_t sb = smem_u32(sm);
    const uint32_t mb0 = sb + NSTAGE * STG64;
    const int tid = threadIdx.x;
    const LaneIdx li = laneidx();   // 256 thr: wm 0..1, wn 0..3
    const int S2 = K >> 6;
    const int KB = K >> 5;
    const long half = (long)((m0 >> 6) & 1) * 4096;

    const char* Ah = (const char*)(AhT) + ((long)(m0 >> 7) * KB) * 8192 + half;
    const char* Al = (const char*)(AlT) + ((long)(m0 >> 7) * KB) * 8192 + half;
    const char* Bh = (const char*)(BhT) + ((long)(n0 >> 7) * KB) * 8192;
    const char* Bl = (const char*)(BlT) + ((long)(n0 >> 7) * KB) * 8192;

    if (tid == 0) { MBINIT(mb0); MBINIT(mb0 + 8); MBINIT(mb0 + 16); }
    __syncthreads();

    auto issue = [&](int s2) {
        const uint32_t mb = mb0 + 8 * (s2 % NSTAGE);
        MBEXPECT(mb, STG64);
#pragma unroll
        for (int j = 0; j < 2; j++) {
            const int k32 = 2 * s2 + j;
            const uint32_t db = sb + (uint32_t)(s2 % NSTAGE) * STG64 + (uint32_t)j * STG32;
            BULK(db,         Ah + (long)k32 * 8192, 4096, mb);
            BULK(db + 4096,  Al + (long)k32 * 8192, 4096, mb);
            BULK(db + 8192,  Bh + (long)k32 * 8192, 8192, mb);
            BULK(db + 16384, Bl + (long)k32 * 8192, 8192, mb);
        }
    };

    if (tid == 0) { issue(0); issue(1); }

    float acc[2][4][4] = {};
    for (int s2 = 0; s2 < S2; s2++) {
        mbwait(mb0 + 8 * (s2 % NSTAGE), (uint32_t)((s2 / NSTAGE) & 1));
        __syncthreads();
        if (tid == 0 && s2 + 2 < S2) issue(s2 + 2);
        const uint32_t stb = sb + (uint32_t)(s2 % NSTAGE) * STG64;
        compute32_split(li, stb, stb + 4096, stb + 8192, stb + 16384, acc);
        compute32_split(li, stb + STG32, stb + STG32 + 4096, stb + STG32 + 8192, stb + STG32 + 16384, acc);
    }

    const int er = li.lane >> 2, ec = (li.lane & 3) * 2;
#pragma unroll
    for (int mt = 0; mt < 2; mt++) {
        const int m = m0 + li.wm * 32 + mt * 16 + er;
#pragma unroll
        for (int nt = 0; nt < 4; nt++) {
            const int n = n0 + li.wn * 32 + nt * 8 + ec;
            const float* c = acc[mt][nt];
            *reinterpret_cast<float2*>(Cf + (long)m * ldc + n) = make_float2(c[0], c[1]);
            *reinterpret_cast<float2*>(Cf + (long)(m + 8) * ldc + n) = make_float2(c[2], c[3]);
        }
    }
}

// ---------------------------------------------------------------------------
// Kernel wrappers
// ---------------------------------------------------------------------------
struct QKVP {
    const bf16 *xh, *xl;
    const __half *xf;
    const bf16 *qwh, *qwl, *kwh, *kwl;
    const __half *vwf;
    const float *qb, *kb, *vb;
    bf16 *qh, *ql, *kh, *kl;      // TILED out
    __half *vf;                   // TILED out
};

__global__ void __launch_bounds__(512) qkv_kernel(QKVP p)
{
    const int bx = blockIdx.x, by = blockIdx.y, bz = blockIdx.z;
    if (bz == 0) {
        gemm_bulk_split(p.xh, p.xl, p.qwh, p.qwl, p.qb, p.qh, p.ql, DD,
                        by * 128, bx * 128, DD);
    } else if (bz == 1) {
        gemm_bulk_split(p.xh, p.xl, p.kwh, p.kwl, p.kb, p.kh, p.kl, DD,
                        by * 128, bx * 128, DD);
    } else {
        const int b = by >> 3, dt = by & 7;
        gemm_bulk_h<2, 1>(p.vwf, p.xf + (long)b * MD, p.vb,
                          nullptr, p.vf + (long)b * MD, TT, dt * 128, bx * 128, DD, DD);
    }
}

__global__ void __launch_bounds__(256) sc_kernel(const bf16* __restrict__ qh, const bf16* __restrict__ ql,
                                                 const bf16* __restrict__ kh, const bf16* __restrict__ kl,
                                                 float* __restrict__ a)
{
    const int bx = blockIdx.x, by = blockIdx.y, b = blockIdx.z;
    if (2 * bx > by) return;
    gemm_bulk_sc(qh + (long)b * MD, ql + (long)b * MD,
                 kh + (long)b * MD, kl + (long)b * MD,
                 a + (long)b * AA, TT, by * 64, bx * 128, DD);
}

__global__ void __launch_bounds__(512) av_kernel(const __half* __restrict__ wf,
                                                 const __half* __restrict__ vf,
                                                 float* __restrict__ o)
{
    const int bx = blockIdx.x, by = blockIdx.y, b = blockIdx.z;
    gemm_bulk_h<0, 0>(wf + (long)b * AA, vf + (long)b * MD, nullptr,
                      o + (long)b * MD, nullptr, DD,
                      by * 128, bx * 128, TT, min(TT, by * 128 + 128));
}

__global__ void __launch_bounds__(512) vocab_kernel(const __half* __restrict__ xn,
                                                    const __half* __restrict__ dwf,
                                                    const float* __restrict__ db,
                                                    float* __restrict__ out)
{
    gemm_bulk_h<1, 0>(xn, dwf, db, out, nullptr, VV, blockIdx.x * 128, blockIdx.y * 128, DD, DD);
}

// ---------------------------------------------------------------------------
// Converters (write TILED layouts) + elementwise
// ---------------------------------------------------------------------------
__global__ void splitw_tiled(const float* __restrict__ src, bf16* __restrict__ h,
                             bf16* __restrict__ l, int nchunks)
{
    int i = blockIdx.x * blockDim.x + threadIdx.x;
    if (i >= nchunks) return;
    const int rg = i >> 7, k = (i & 127) << 3;
    const float4* s = reinterpret_cast<const float4*>(src + (long)rg * 1024 + k);
    float4 v0 = s[0], v1 = s[1];
    bf16 hh[8], ll[8];
    bsplit(v0.x, hh[0], ll[0]); bsplit(v0.y, hh[1], ll[1]);
    bsplit(v0.z, hh[2], ll[2]); bsplit(v0.w, hh[3], ll[3]);
    bsplit(v1.x, hh[4], ll[4]); bsplit(v1.y, hh[5], ll[5]);
    bsplit(v1.z, hh[6], ll[6]); bsplit(v1.w, hh[7], ll[7]);
    long off = toff(rg, k, 1024);
    *reinterpret_cast<uint4*>(h + off) = *reinterpret_cast<uint4*>(hh);
    *reinterpret_cast<uint4*>(l + off) = *reinterpret_cast<uint4*>(ll);
}

__global__ void tohalf_tiled(const float* __restrict__ src, __half* __restrict__ dst, int nchunks)
{
    int i = blockIdx.x * blockDim.x + threadIdx.x;
    if (i >= nchunks) return;
    const int rg = i >> 7, k = (i & 127) << 3;
    const float4* s = reinterpret_cast<const float4*>(src + (long)rg * 1024 + k);
    float4 v0 = s[0], v1 = s[1];
    __half hh[8];
    *reinterpret_cast<__half2*>(hh)     = __floats2half2_rn(v0.x, v0.y);
    *reinterpret_cast<__half2*>(hh + 2) = __floats2half2_rn(v0.z, v0.w);
    *reinterpret_cast<__half2*>(hh + 4) = __floats2half2_rn(v1.x, v1.y);
    *reinterpret_cast<__half2*>(hh + 6) = __floats2half2_rn(v1.z, v1.w);
    *reinterpret_cast<uint4*>(dst + toff(rg, k, 1024)) = *reinterpret_cast<uint4*>(hh);
}

__device__ __forceinline__ void store_x3(float4 v, int rg, int k, float* X,
                                         bf16* xh, bf16* xl, __half* xf)
{
    if (X) *reinterpret_cast<float4*>(X + (long)rg * DD + k) = v;
    bf16 h0, l0, h1, l1, h2, l2, h3, l3;
    bsplit(v.x, h0, l0); bsplit(v.y, h1, l1); bsplit(v.z, h2, l2); bsplit(v.w, h3, l3);
    long off = toff(rg, k, DD);
    *reinterpret_cast<__nv_bfloat162*>(xh + off)     = __halves2bfloat162(h0, h1);
    *reinterpret_cast<__nv_bfloat162*>(xh + off + 2) = __halves2bfloat162(h2, h3);
    *reinterpret_cast<__nv_bfloat162*>(xl + off)     = __halves2bfloat162(l0, l1);
    *reinterpret_cast<__nv_bfloat162*>(xl + off + 2) = __halves2bfloat162(l2, l3);
    *reinterpret_cast<__half2*>(xf + off)     = __floats2half2_rn(v.x, v.y);
    *reinterpret_cast<__half2*>(xf + off + 2) = __floats2half2_rn(v.z, v.w);
}

__global__ void embed_pe_kernel(const int* __restrict__ src, const float* __restrict__ pe,
                                const float* __restrict__ embed, float* __restrict__ x,
                                bf16* __restrict__ xh, bf16* __restrict__ xl, __half* __restrict__ xf)
{
    int row = blockIdx.x, b = row >> 10;
    long tok = src[row];
    const float4* e = reinterpret_cast<const float4*>(embed + tok * (long)DD);
    const float4* p = reinterpret_cast<const float4*>(pe + (long)b * DD);
    int i = threadIdx.x;
    float4 ev = e[i], pv = p[i];
    float4 v = make_float4(ev.x + pv.x, ev.y + pv.y, ev.z + pv.z, ev.w + pv.w);
    store_x3(v, row, i * 4, x, xh, xl, xf);
}

__global__ void softmax_kernel(const float* __restrict__ A, __half* __restrict__ Wf)
{
    int t = blockIdx.x, b = blockIdx.y;
    const float* row = A + ((long)b * TT + t) * TT;
    __half* wf = Wf + (long)b * AA;
    int n = t + 1, i = threadIdx.x;
    __shared__ float red[256];
    __shared__ float rowe[TT];
    float m = -1e30f;
    for (int s = i; s < n; s += 256) m = fmaxf(m, row[s]);
    red[i] = m; __syncthreads();
    for (int st = 128; st > 0; st >>= 1) { if (i < st) red[i] = fmaxf(red[i], red[i + st]); __syncthreads(); }
    m = red[0]; __syncthreads();
    float sum = 0.f;
    for (int s = i; s < n; s += 256) { float e = expf(row[s] - m); rowe[s] = e; sum += e; }
    red[i] = sum; __syncthreads();
    for (int st = 128; st > 0; st >>= 1) { if (i < st) red[i] += red[i + st]; __syncthreads(); }
    float inv = 1.0f / red[0];
    // write TILED (pairs: s even, s+1): both elements in same 8-chunk
    for (int s2 = i; s2 < TT / 2; s2 += 256) {
        int s = s2 * 2;
        float w0 = (s < n) ? rowe[s] * inv : 0.f;
        float w1 = (s + 1 < n) ? rowe[s + 1] * inv : 0.f;
        *reinterpret_cast<__half2*>(wf + toff(t, s, TT)) = __floats2half2_rn(w0, w1);
    }
}

__global__ void ln_res_kernel(const float* __restrict__ O, const float* __restrict__ w,
                              const float* __restrict__ bb, float* __restrict__ X,
                              bf16* __restrict__ xh, bf16* __restrict__ xl, __half* __restrict__ xf)
{
    int row = blockIdx.x, i = threadIdx.x;
    const float4 o = reinterpret_cast<const float4*>(O + (long)row * DD)[i];
    float4* x4 = reinterpret_cast<float4*>(X + (long)row * DD);
    __shared__ float red[256];
    red[i] = o.x + o.y + o.z + o.w; __syncthreads();
    for (int st = 128; st > 0; st >>= 1) { if (i < st) red[i] += red[i + st]; __syncthreads(); }
    float mu = red[0] * (1.0f / DD); __syncthreads();
    float dx = o.x - mu, dy = o.y - mu, dz = o.z - mu, dw_ = o.w - mu;
    red[i] = dx * dx + dy * dy + dz * dz + dw_ * dw_; __syncthreads();
    for (int st = 128; st > 0; st >>= 1) { if (i < st) red[i] += red[i + st]; __syncthreads(); }
    float rstd = rsqrtf(red[0] * (1.0f / DD) + 1e-6f);
    float4 wv = reinterpret_cast<const float4*>(w)[i];
    float4 bv = reinterpret_cast<const float4*>(bb)[i];
    float4 xv = x4[i];
    xv.x += dx * rstd * wv.x + bv.x;
    xv.y += dy * rstd * wv.y + bv.y;
    xv.z += dz * rstd * wv.z + bv.z;
    xv.w += dw_ * rstd * wv.w + bv.w;
    x4[i] = xv;
    store_x3(xv, row, i * 4, nullptr, xh, xl, xf);
}

__global__ void final_ln_kernel(const float* __restrict__ X, const float* __restrict__ fw,
                                const float* __restrict__ fb, __half* __restrict__ Y)  // Y tiled
{
    int row = blockIdx.x, i = threadIdx.x;
    const float4 x = reinterpret_cast<const float4*>(X + (long)row * DD)[i];
    __shared__ float red[256];
    red[i] = x.x + x.y + x.z + x.w; __syncthreads();
    for (int st = 128; st > 0; st >>= 1) { if (i < st) red[i] += red[i + st]; __syncthreads(); }
    float mu = red[0] * (1.0f / DD); __syncthreads();
    float dx = x.x - mu, dy = x.y - mu, dz = x.z - mu, dw_ = x.w - mu;
    red[i] = dx * dx + dy * dy + dz * dz + dw_ * dw_; __syncthreads();
    for (int st = 128; st > 0; st >>= 1) { if (i < st) red[i] += red[i + st]; __syncthreads(); }
    float rstd = rsqrtf(red[0] * (1.0f / DD) + 1e-5f);
    float4 wv = reinterpret_cast<const float4*>(fw)[i];
    float4 bv = reinterpret_cast<const float4*>(fb)[i];
    long off = toff(row, i * 4, DD);
    *reinterpret_cast<__half2*>(Y + off)     = __floats2half2_rn(dx * rstd * wv.x + bv.x, dy * rstd * wv.y + bv.y);
    *reinterpret_cast<__half2*>(Y + off + 2) = __floats2half2_rn(dz * rstd * wv.z + bv.z, dw_ * rstd * wv.w + bv.w);
}

// ---------------------------------------------------------------------------
extern "C" void kernel_launch(void* const* d_in, const int* in_sizes, int n_in,
                              void* d_out, int out_size)
{
    const int*   src = (const int*)d_in[0];
    const float* pe  = (const float*)d_in[1];
    const float* emb = (const float*)d_in[2];
    const float* qw  = (const float*)d_in[3];
    const float* qb  = (const float*)d_in[4];
    const float* kw  = (const float*)d_in[5];
    const float* kb  = (const float*)d_in[6];
    const float* vw  = (const float*)d_in[7];
    const float* vb  = (const float*)d_in[8];
    const float* lnw = (const float*)d_in[9];
    const float* lnb = (const float*)d_in[10];
    const float* fw  = (const float*)d_in[11];
    const float* fb  = (const float*)d_in[12];
    const float* dw  = (const float*)d_in[13];
    const float* db  = (const float*)d_in[14];
    float* out = (float*)d_out;

#define GA(sym, var) void* var##_; cudaGetSymbolAddress(&var##_, sym)
    GA(g_x, x);  GA(g_a, a);  GA(g_o, o);
    GA(g_xh, xh); GA(g_xl, xl); GA(g_xf, xf);
    GA(g_qh, qh); GA(g_ql, ql); GA(g_kh, kh); GA(g_kl, kl);
    GA(g_vf, vf); GA(g_wf, wf);
    GA(g_qwh, qwh); GA(g_qwl, qwl); GA(g_kwh, kwh); GA(g_kwl, kwl);
    GA(g_vwf, vwf); GA(g_dwf, dwf); GA(g_xnf, xnf);
#undef GA

    const int SMB = NSTAGE * 65536 + 64;   // 196672 (bulk split)
    const int SMS = NSTAGE * 49152 + 64;   // 147520 (bulk sc)
    const int SMH = NSTAGE * 32768 + 64;   // 98368  (bulk fp16)
    cudaFuncSetAttribute(qkv_kernel,   cudaFuncAttributeMaxDynamicSharedMemorySize, SMB);
    cudaFuncSetAttribute(sc_kernel,    cudaFuncAttributeMaxDynamicSharedMemorySize, SMS);
    cudaFuncSetAttribute(av_kernel,    cudaFuncAttributeMaxDynamicSharedMemorySize, SMH);
    cudaFuncSetAttribute(vocab_kernel, cudaFuncAttributeMaxDynamicSharedMemorySize, SMH);

    // per-launch weight conversions -> TILED layouts (deterministic, idempotent)
    {
        const int ncw = LL * DD * DD / 8;
        splitw_tiled<<<(ncw + 511) / 512, 512>>>(qw, (bf16*)qwh_, (bf16*)qwl_, ncw);
        splitw_tiled<<<(ncw + 511) / 512, 512>>>(kw, (bf16*)kwh_, (bf16*)kwl_, ncw);
        tohalf_tiled<<<(ncw + 511) / 512, 512>>>(vw, (__half*)vwf_, ncw);
        const int ncd = VV * DD / 8;
        tohalf_tiled<<<(ncd + 511) / 512, 512>>>(dw, (__half*)dwf_, ncd);
    }

    embed_pe_kernel<<<BB * TT, 256>>>(src, pe, emb, (float*)x_, (bf16*)xh_, (bf16*)xl_, (__half*)xf_);

    dim3 gqkv(DD / 128, (BB * TT) / 128, 3);
    dim3 gsc(TT / 128, TT / 64, BB);
    dim3 gav(TT / 128, TT / 128, BB);
    for (int l = 0; l < LL; l++) {
        const long wo = (long)l * DD * DD;
        QKVP p;
        p.xh = (const bf16*)xh_; p.xl = (const bf16*)xl_; p.xf = (const __half*)xf_;
        p.qwh = (const bf16*)qwh_ + wo; p.qwl = (const bf16*)qwl_ + wo;
        p.kwh = (const bf16*)kwh_ + wo; p.kwl = (const bf16*)kwl_ + wo;
        p.vwf = (const __half*)vwf_ + wo;
        p.qb = qb + l * DD; p.kb = kb + l * DD; p.vb = vb + l * DD;
        p.qh = (bf16*)qh_; p.ql = (bf16*)ql_;
        p.kh = (bf16*)kh_; p.kl = (bf16*)kl_;
        p.vf = (__half*)vf_;
        qkv_kernel<<<gqkv, 512, SMB>>>(p);
        sc_kernel<<<gsc, 256, SMS>>>((const bf16*)qh_, (const bf16*)ql_,
                                     (const bf16*)kh_, (const bf16*)kl_, (float*)a_);
        softmax_kernel<<<dim3(TT, BB), 256>>>((const float*)a_, (__half*)wf_);
        av_kernel<<<gav, 512, SMH>>>((const __half*)wf_, (const __half*)vf_, (float*)o_);
        ln_res_kernel<<<BB * TT, 256>>>((const float*)o_, lnw + l * DD, lnb + l * DD,
                                        (float*)x_, (bf16*)xh_, (bf16*)xl_, (__half*)xf_);
    }

    final_ln_kernel<<<BB * TT, 256>>>((const float*)x_, fw, fb, (__half*)xnf_);
    dim3 gf((BB * TT) / 128, VV / 128);
    vocab_kernel<<<gf, 512, SMH>>>((const __half*)xnf_, (const __half*)dwf_, db, out);
}